// round 8
// baseline (speedup 1.0000x reference)
#include <cuda_runtime.h>
#include <cuda_bf16.h>
#include <math.h>
#include <stdint.h>

// ---------------- problem constants ----------------
#define NB    64
#define NPG   20
#define NN    (NB*NPG)          // 1280
#define NE    (NB*NPG*(NPG-1))  // 24320
#define NPAIR_G (NPG*(NPG-1)/2) // 190
#define NP    (NB*NPAIR_G)      // 12160
#define HD    512
#define TDm   256
#define NLAY  6
#define EINW  2313
#define DEG   (NPG-1)           // 19

#define TWO_PI_F 6.2831853071795864f

#define OFF_UD   0
#define OFF_SRC  3
#define OFF_DST  515
#define OFF_LAT  1027
#define OFF_FEMB 1033
#define OFF_NA   1801

#define FLAG_ACC   1
#define FLAG_SILU  2
#define FLAG_SPLIT 4

typedef unsigned long long u64;
typedef __nv_bfloat16 bf16;

// ---------------- scratch (device globals) ----------------
__device__ __align__(16) float g_h   [NN*HD];
__device__ __align__(16) float g_Xsd [NN*1024];   // [Xs | Xd]
__device__ __align__(16) float g_T1  [NN*HD];
__device__ __align__(16) float g_hF  [NN*HD];
__device__ __align__(16) float g_S   [(size_t)NP*HD];
__device__ __align__(16) float g_C   [(size_t)NP*HD];
__device__ __align__(16) float g_E2  [(size_t)NE*HD];
__device__ __align__(16) float g_ud  [NP*3];
__device__ __align__(16) float g_ltl [NB*9];
__device__ __align__(16) float g_econst[NLAY*NB*HD];
__device__ __align__(16) float g_v   [HD];
__device__ int g_arow[NN];

// bf16 activation planes
__device__ __align__(16) bf16 g_sch [(size_t)NP*768];
__device__ __align__(16) bf16 g_scl [(size_t)NP*768];
__device__ __align__(16) bf16 g_E1h [(size_t)NE*HD];
__device__ __align__(16) bf16 g_E1l [(size_t)NE*HD];
__device__ __align__(16) bf16 g_cath[NN*1024];    // [hn | agg]
__device__ __align__(16) bf16 g_catl[NN*1024];
__device__ __align__(16) bf16 g_T1h [NN*HD];
__device__ __align__(16) bf16 g_T1l [NN*HD];

// bf16 weight planes (K-major as in source)
__device__ __align__(16) bf16 g_Wsdh[(size_t)NLAY*HD*1024];  // [Wsrc|Wdst] packed
__device__ __align__(16) bf16 g_Wsdl[(size_t)NLAY*HD*1024];
__device__ __align__(16) bf16 g_Wfh [(size_t)NLAY*768*HD];
__device__ __align__(16) bf16 g_Wfl [(size_t)NLAY*768*HD];
__device__ __align__(16) bf16 g_We2h[(size_t)NLAY*HD*HD];
__device__ __align__(16) bf16 g_We2l[(size_t)NLAY*HD*HD];
__device__ __align__(16) bf16 g_Wn1h[(size_t)NLAY*2*HD*HD];
__device__ __align__(16) bf16 g_Wn1l[(size_t)NLAY*2*HD*HD];
__device__ __align__(16) bf16 g_Wn2h[(size_t)NLAY*HD*HD];
__device__ __align__(16) bf16 g_Wn2l[(size_t)NLAY*HD*HD];

// ---------------- helpers ----------------
__device__ __forceinline__ float warp_sum(float v){
    #pragma unroll
    for (int o = 16; o > 0; o >>= 1) v += __shfl_down_sync(0xffffffffu, v, o);
    return v;
}
__device__ __forceinline__ float silu_f(float v){ return v / (1.f + expf(-v)); }
__device__ __forceinline__ void splitf(float v, bf16 &h, bf16 &l){
    h = __float2bfloat16(v);
    l = __float2bfloat16(v - __bfloat162float(h));
}
__device__ __forceinline__ uint32_t sm_u32(const void* p){
    return (uint32_t)__cvta_generic_to_shared(p);
}
__device__ __forceinline__ void ldsm_x4(uint32_t &r0, uint32_t &r1, uint32_t &r2, uint32_t &r3, uint32_t a){
    asm volatile("ldmatrix.sync.aligned.m8n8.x4.shared.b16 {%0,%1,%2,%3}, [%4];"
        : "=r"(r0),"=r"(r1),"=r"(r2),"=r"(r3) : "r"(a));
}
__device__ __forceinline__ void ldsm_x4t(uint32_t &r0, uint32_t &r1, uint32_t &r2, uint32_t &r3, uint32_t a){
    asm volatile("ldmatrix.sync.aligned.m8n8.x4.trans.shared.b16 {%0,%1,%2,%3}, [%4];"
        : "=r"(r0),"=r"(r1),"=r"(r2),"=r"(r3) : "r"(a));
}
__device__ __forceinline__ void mma_bf16(float* c, const uint32_t* a, const uint32_t* b){
    asm volatile(
      "mma.sync.aligned.m16n8k16.row.col.f32.bf16.bf16.f32 "
      "{%0,%1,%2,%3}, {%4,%5,%6,%7}, {%8,%9}, {%0,%1,%2,%3};"
      : "+f"(c[0]),"+f"(c[1]),"+f"(c[2]),"+f"(c[3])
      : "r"(a[0]),"r"(a[1]),"r"(a[2]),"r"(a[3]), "r"(b[0]),"r"(b[1]));
}
__device__ __forceinline__ void cp16(uint32_t s, const void* g){
    asm volatile("cp.async.cg.shared.global [%0], [%1], 16;" :: "r"(s), "l"(g));
}
#define CP_COMMIT() asm volatile("cp.async.commit_group;" ::: "memory")
template<int N> __device__ __forceinline__ void cp_wait(){
    asm volatile("cp.async.wait_group %0;" :: "n"(N) : "memory");
}

// ---------------- split-bf16 tensor-core GEMM (cp.async 3-stage, multi-desc) --------
// C = (Ah+Al) @ (Bh+Bl): AhBh + AhBl + AlBh, fp32 accumulate.
// M%128==0, N%128==0, K%32==0, K>=64. Block 256 threads, tile 128x128, K-chunk 32.
// Stage layout (bf16 elems): Ah[128][40] @0, Al @5120, Bh[32][136] @10240, Bl @14592.
#define STG_ELEMS 18944
#define NSTAGE 3
#define SMEM_MMA_BYTES (NSTAGE*STG_ELEMS*2)

struct GemmDesc {
    const bf16 *Ah, *Al, *Bh, *Bl;
    float* C;
    const float *bias, *res;
    bf16 *Oh, *Ol;
    int lda, ldb, ldc, K, nbx, flags;
};

__device__ __forceinline__ void mm_load_stage(bf16* st, int tid, const GemmDesc& d,
                                              int row0, int col0, int k0)
{
    #pragma unroll
    for (int t = 0; t < 2; t++) {
        int lin = tid + t*256;
        int r = lin >> 2, c8 = (lin & 3) * 8;
        cp16(sm_u32(st +          r*40 + c8), d.Ah + (size_t)(row0+r)*d.lda + k0 + c8);
        cp16(sm_u32(st +  5120 +  r*40 + c8), d.Al + (size_t)(row0+r)*d.lda + k0 + c8);
        int rb = lin >> 4, cb = (lin & 15) * 8;
        cp16(sm_u32(st + 10240 + rb*136 + cb), d.Bh + (size_t)(k0+rb)*d.ldb + col0 + cb);
        cp16(sm_u32(st + 14592 + rb*136 + cb), d.Bl + (size_t)(k0+rb)*d.ldb + col0 + cb);
    }
    CP_COMMIT();
}

__device__ __forceinline__ void mm_compute_stage(const bf16* st, float acc[4][4][4],
                                                 int wm, int wn, int lane)
{
    const bf16* ah_ = st;
    const bf16* al_ = st + 5120;
    const bf16* bh_ = st + 10240;
    const bf16* bl_ = st + 14592;
    #pragma unroll
    for (int ks = 0; ks < 32; ks += 16) {
        uint32_t ah[4][4], al[4][4], bh[4][2], bl[4][2];
        #pragma unroll
        for (int mt = 0; mt < 4; mt++) {
            int rr = wm + mt*16 + (lane & 15);
            int cc = ks + (lane >> 4)*8;
            ldsm_x4(ah[mt][0],ah[mt][1],ah[mt][2],ah[mt][3], sm_u32(ah_ + rr*40 + cc));
            ldsm_x4(al[mt][0],al[mt][1],al[mt][2],al[mt][3], sm_u32(al_ + rr*40 + cc));
        }
        #pragma unroll
        for (int nt2 = 0; nt2 < 2; nt2++) {
            int rr = ks + (lane & 15);
            int cc = wn + nt2*16 + (lane >> 4)*8;
            uint32_t r0,r1,r2,r3;
            ldsm_x4t(r0,r1,r2,r3, sm_u32(bh_ + rr*136 + cc));
            bh[nt2*2][0]=r0; bh[nt2*2][1]=r1; bh[nt2*2+1][0]=r2; bh[nt2*2+1][1]=r3;
            ldsm_x4t(r0,r1,r2,r3, sm_u32(bl_ + rr*136 + cc));
            bl[nt2*2][0]=r0; bl[nt2*2][1]=r1; bl[nt2*2+1][0]=r2; bl[nt2*2+1][1]=r3;
        }
        #pragma unroll
        for (int mt = 0; mt < 4; mt++)
            #pragma unroll
            for (int nt = 0; nt < 4; nt++) {
                mma_bf16(acc[mt][nt], ah[mt], bh[nt]);
                mma_bf16(acc[mt][nt], ah[mt], bl[nt]);
                mma_bf16(acc[mt][nt], al[mt], bh[nt]);
            }
    }
}

__global__ __launch_bounds__(256)
void mma_gemm3(GemmDesc d0, GemmDesc d1, GemmDesc d2, int c0, int c1)
{
    extern __shared__ __align__(16) char dsmem[];
    bf16* stage[NSTAGE];
    #pragma unroll
    for (int s = 0; s < NSTAGE; s++) stage[s] = (bf16*)dsmem + (size_t)s*STG_ELEMS;

    int b = blockIdx.x;
    GemmDesc d;
    if (b < c0)       { d = d0; }
    else if (b < c1)  { d = d1; b -= c0; }
    else              { d = d2; b -= c1; }
    const int row0 = (b / d.nbx) * 128;
    const int col0 = (b % d.nbx) * 128;

    const int tid  = threadIdx.x;
    const int warp = tid >> 5, lane = tid & 31;
    const int wm = (warp >> 2) * 64;
    const int wn = (warp & 3) * 32;

    float acc[4][4][4];
    #pragma unroll
    for (int i = 0; i < 4; i++)
        #pragma unroll
        for (int j = 0; j < 4; j++)
            #pragma unroll
            for (int k = 0; k < 4; k++) acc[i][j][k] = 0.f;

    const int nch = d.K >> 5;   // >= 2 for all call sites
    mm_load_stage(stage[0], tid, d, row0, col0, 0);
    mm_load_stage(stage[1], tid, d, row0, col0, 32);

    for (int kc = 0; kc < nch; kc++) {
        cp_wait<1>();
        __syncthreads();
        if (kc + 2 < nch) mm_load_stage(stage[(kc+2)%NSTAGE], tid, d, row0, col0, (kc+2)*32);
        else CP_COMMIT();
        mm_compute_stage(stage[kc%NSTAGE], acc, wm, wn, lane);
    }

    // epilogue (validated fragment layout)
    const int flags = d.flags;
    #pragma unroll
    for (int mt = 0; mt < 4; mt++) {
        #pragma unroll
        for (int nt = 0; nt < 4; nt++) {
            #pragma unroll
            for (int half = 0; half < 2; half++) {
                int rr = row0 + wm + mt*16 + (lane >> 2) + half*8;
                int cc = col0 + wn + nt*8 + (lane & 3)*2;
                float v0 = acc[mt][nt][half*2 + 0];
                float v1 = acc[mt][nt][half*2 + 1];
                size_t o = (size_t)rr*d.ldc + cc;
                if (flags & FLAG_ACC)  { v0 += d.C[o]; v1 += d.C[o+1]; }
                if (d.bias)            { v0 += d.bias[cc]; v1 += d.bias[cc+1]; }
                if (flags & FLAG_SILU) { v0 = silu_f(v0); v1 = silu_f(v1); }
                if (d.res)             { v0 += d.res[o]; v1 += d.res[o+1]; }
                *(float2*)(d.C + o) = make_float2(v0, v1);
                if (flags & FLAG_SPLIT) {
                    bf16 h0,l0,h1,l1;
                    splitf(v0,h0,l0); splitf(v1,h1,l1);
                    *(__nv_bfloat162*)(d.Oh + o) = __nv_bfloat162(h0, h1);
                    *(__nv_bfloat162*)(d.Ol + o) = __nv_bfloat162(l0, l1);
                }
            }
        }
    }
}

// ---------------- FFMA2 SGEMM (prologue h0 only) ----
__device__ __forceinline__ u64 pack2(float x, float y){
    u64 r; asm("mov.b64 %0, {%1, %2};" : "=l"(r) : "f"(x), "f"(y)); return r;
}
__device__ __forceinline__ void unpack2(u64 v, float &x, float &y){
    asm("mov.b64 {%0, %1}, %2;" : "=f"(x), "=f"(y) : "l"(v));
}
__device__ __forceinline__ void ffma2(u64 &acc, u64 a, u64 b){
    asm("fma.rn.f32x2 %0, %1, %2, %0;" : "+l"(acc) : "l"(a), "l"(b));
}
template<int BM,int BN,int BK,int TM,int TN>
__global__ __launch_bounds__((BM/TM)*(BN/TN))
void sgemm2_kernel(int M, int N, int K,
                   const float* __restrict__ A, int lda,
                   const float* __restrict__ B, int ldb,
                   float* __restrict__ C, int ldc,
                   const int* __restrict__ arow)
{
    __shared__ __align__(16) float As[BK][BM];
    __shared__ __align__(16) float Bs[BK][BN];
    const int tid = threadIdx.x;
    const int tx  = tid % (BN/TN);
    const int ty  = tid / (BN/TN);
    const int row0 = blockIdx.y * BM;
    const int col0 = blockIdx.x * BN;
    constexpr int AVPR = BK/4;
    const int a_r = tid / AVPR;
    const int a_c = (tid % AVPR) * 4;
    constexpr int BVPR = BN/4;
    const int b_r = tid / BVPR;
    const int b_c = (tid % BVPR) * 4;
    const float* Arow = A + (size_t)(arow ? arow[row0 + a_r] : (row0 + a_r)) * lda;

    u64 acc[TM][TN/2];
    #pragma unroll
    for (int i = 0; i < TM; i++)
        #pragma unroll
        for (int j = 0; j < TN/2; j++) acc[i][j] = 0ull;

    for (int k0 = 0; k0 < K; k0 += BK) {
        float4 av = *(const float4*)(Arow + k0 + a_c);
        As[a_c+0][a_r] = av.x; As[a_c+1][a_r] = av.y;
        As[a_c+2][a_r] = av.z; As[a_c+3][a_r] = av.w;
        *(float4*)&Bs[b_r][b_c] = *(const float4*)(B + (size_t)(k0 + b_r)*ldb + col0 + b_c);
        __syncthreads();
        #pragma unroll
        for (int kk = 0; kk < BK; kk++) {
            float a[TM];
            #pragma unroll
            for (int i = 0; i < TM; i += 4) {
                float4 t = *(const float4*)&As[kk][ty*TM + i];
                a[i]=t.x; a[i+1]=t.y; a[i+2]=t.z; a[i+3]=t.w;
            }
            u64 ap[TM];
            #pragma unroll
            for (int i = 0; i < TM; i++) ap[i] = pack2(a[i], a[i]);
            u64 bp[TN/2];
            #pragma unroll
            for (int j = 0; j < TN/2; j += 2) {
                ulonglong2 t = *(const ulonglong2*)&Bs[kk][tx*TN + 2*j];
                bp[j] = t.x; bp[j+1] = t.y;
            }
            #pragma unroll
            for (int i = 0; i < TM; i++)
                #pragma unroll
                for (int j = 0; j < TN/2; j++)
                    ffma2(acc[i][j], ap[i], bp[j]);
        }
        __syncthreads();
    }
    #pragma unroll
    for (int i = 0; i < TM; i++) {
        const int r = row0 + ty*TM + i;
        #pragma unroll
        for (int j = 0; j < TN/2; j++) {
            const int c = col0 + tx*TN + 2*j;
            float v0, v1; unpack2(acc[i][j], v0, v1);
            C[(size_t)r*ldc + c]   = v0;
            C[(size_t)r*ldc + c+1] = v1;
        }
    }
}

// ---------------- glue kernels ----------------
__global__ void split_kernel(const float* __restrict__ in, bf16* __restrict__ oh,
                             bf16* __restrict__ ol, int n){
    int i = blockIdx.x*256 + threadIdx.x;
    if (i < n) { bf16 h,l; splitf(in[i], h, l); oh[i]=h; ol[i]=l; }
}

// pack [Wsrc | Wdst] (512 x 1024) and split
__global__ void pack_sd_kernel(const float* __restrict__ We1_l,
                               bf16* __restrict__ oh, bf16* __restrict__ ol){
    int idx = blockIdx.x*256 + threadIdx.x;   // 512*1024 total
    int k = idx >> 10, c = idx & 1023;
    float v = (c < 512) ? We1_l[(size_t)(OFF_SRC + k)*HD + c]
                        : We1_l[(size_t)(OFF_DST + k)*HD + (c - 512)];
    bf16 h,l; splitf(v,h,l);
    oh[idx]=h; ol[idx]=l;
}

__global__ void atomidx_kernel(const int* __restrict__ at){
    int n = blockIdx.x*256 + threadIdx.x;
    if (n < NN) g_arow[n] = max(at[n]-1, 0);
}

__global__ void vtime_kernel(const float* __restrict__ Wt, const float* __restrict__ Wl){
    int j = blockIdx.x*256 + threadIdx.x;
    if (j >= HD) return;
    float acc = 0.f;
    for (int k = 0; k < TDm; k++) acc += Wt[k] * Wl[(size_t)(HD + k)*HD + j];
    g_v[j] = acc;
}

__global__ void add_tv_kernel(const float* __restrict__ t, const int* __restrict__ n2g){
    int n = blockIdx.x; int j = threadIdx.x;
    g_h[(size_t)n*HD + j] += t[n2g[n]] * g_v[j];
}

__global__ void lattice_kernel(const float* __restrict__ lp){
    int b = blockIdx.x*64 + threadIdx.x;
    if (b >= NB) return;
    const float LM[3] = {1.575442910194397f, 1.7017393112182617f, 1.9781638383865356f};
    const float LS[3] = {0.24437622725963593f, 0.26526379585266113f, 0.3535512685775757f};
    float len[3], ang[3];
    #pragma unroll
    for (int i = 0; i < 3; i++) {
        len[i] = expf(lp[b*6+i]*LS[i] + LM[i]);
        float x = lp[b*6+3+i];
        float sg = 1.f/(1.f+expf(-x));
        ang[i] = (59.9f + 60.2f*sg) * (3.14159265358979323846f/180.f);
    }
    float c0=cosf(ang[0]), c1=cosf(ang[1]), c2=cosf(ang[2]);
    float s0=sinf(ang[0]), s1=sinf(ang[1]);
    float val = (c0*c1 - c2) / (s0*s1);
    val = fminf(1.f, fmaxf(-1.f, val));
    float gs = acosf(val);
    float L[3][3];
    L[0][0]=len[0]*s1;            L[0][1]=0.f;                 L[0][2]=len[0]*c1;
    L[1][0]=-len[1]*s0*cosf(gs);  L[1][1]=len[1]*s0*sinf(gs);  L[1][2]=len[1]*c0;
    L[2][0]=0.f;                  L[2][1]=0.f;                 L[2][2]=len[2];
    #pragma unroll
    for (int i = 0; i < 3; i++)
        #pragma unroll
        for (int k = 0; k < 3; k++)
            g_ltl[b*9 + i*3 + k] = L[i][0]*L[k][0] + L[i][1]*L[k][1] + L[i][2]*L[k][2];
}

__global__ void pair_geom_kernel(const float* __restrict__ fc)
{
    const int p = blockIdx.x;
    __shared__ float d[3];
    if (threadIdx.x == 0) {
        int g = p / NPAIR_G, q = p % NPAIR_G;
        int i = 0, base = 0;
        while (base + (DEG - i) <= q) { base += DEG - i; i++; }
        int j = i + 1 + (q - base);
        int ni = g*NPG + i, nj = g*NPG + j;
        float dd[3];
        #pragma unroll
        for (int k = 0; k < 3; k++) {
            float z = TWO_PI_F * (fc[nj*3+k] - fc[ni*3+k]);
            dd[k] = atan2f(sinf(z), cosf(z)) * (1.f/TWO_PI_F);
        }
        float dot[3];
        #pragma unroll
        for (int k = 0; k < 3; k++)
            dot[k] = g_ltl[g*9+k*3+0]*dd[0] + g_ltl[g*9+k*3+1]*dd[1] + g_ltl[g*9+k*3+2]*dd[2];
        float nrm = sqrtf(dot[0]*dot[0] + dot[1]*dot[1] + dot[2]*dot[2]) + 1e-12f;
        #pragma unroll
        for (int k = 0; k < 3; k++) {
            g_ud[p*3+k] = dot[k] / nrm;
            d[k] = dd[k];
        }
    }
    __syncthreads();
    int idx = threadIdx.x;          // 384 threads
    int dim = idx >> 7, k = idx & 127;
    float ang = d[dim] * (TWO_PI_F * (float)k);
    float s, c; sincosf(ang, &s, &c);
    bf16 h,l;
    splitf(s,h,l);
    g_sch[(size_t)p*768 + idx] = h; g_scl[(size_t)p*768 + idx] = l;
    splitf(c,h,l);
    g_sch[(size_t)p*768 + 384 + idx] = h; g_scl[(size_t)p*768 + 384 + idx] = l;
}

__global__ void econst_kernel(const float* __restrict__ We1, const float* __restrict__ be1,
                              const float* __restrict__ Wna, const float* __restrict__ lp,
                              const int* __restrict__ numat)
{
    const int l = blockIdx.x / NB, b = blockIdx.x % NB;
    const int j = threadIdx.x;
    const float* W = We1 + (size_t)l*EINW*HD;
    float acc = be1[l*HD + j];
    #pragma unroll
    for (int k = 0; k < 6; k++)
        acc += lp[b*6+k] * W[(size_t)(OFF_LAT+k)*HD + j];
    const float* na = Wna + (size_t)l*100*HD + (size_t)max(numat[b]-1,0)*HD;
    for (int k = 0; k < HD; k++)
        acc += na[k] * W[(size_t)(OFF_NA+k)*HD + j];
    g_econst[((size_t)l*NB + b)*HD + j] = acc;
}

// LayerNorm; optional fp32 out (stride HD) + bf16 planes (stride ldp)
__global__ void ln_kernel(const float* __restrict__ x, const float* __restrict__ g,
                          const float* __restrict__ b, float* __restrict__ y,
                          bf16* __restrict__ yh, bf16* __restrict__ yl, int ldp)
{
    const int n = blockIdx.x;
    const int j = threadIdx.x;
    const float* xr = x + (size_t)n*HD;
    float v0 = xr[j], v1 = xr[j+256];
    __shared__ float sh[8];
    int lane = j & 31, w = j >> 5;
    float s = warp_sum(v0 + v1);
    if (lane == 0) sh[w] = s;
    __syncthreads();
    if (w == 0) { float t = (lane < 8) ? sh[lane] : 0.f; t = warp_sum(t); if (lane==0) sh[0]=t; }
    __syncthreads();
    float mean = sh[0] * (1.f/HD);
    __syncthreads();
    float d0 = v0 - mean, d1 = v1 - mean;
    float q = warp_sum(d0*d0 + d1*d1);
    if (lane == 0) sh[w] = q;
    __syncthreads();
    if (w == 0) { float t = (lane < 8) ? sh[lane] : 0.f; t = warp_sum(t); if (lane==0) sh[0]=t; }
    __syncthreads();
    float inv = rsqrtf(sh[0]*(1.f/HD) + 1e-5f);
    float o0 = d0*inv*g[j]     + b[j];
    float o1 = d1*inv*g[j+256] + b[j+256];
    if (y) {
        y[(size_t)n*HD + j]     = o0;
        y[(size_t)n*HD + j+256] = o1;
    }
    bf16 hh,ll;
    splitf(o0,hh,ll); yh[(size_t)n*ldp+j]=hh;     yl[(size_t)n*ldp+j]=ll;
    splitf(o1,hh,ll); yh[(size_t)n*ldp+j+256]=hh; yl[(size_t)n*ldp+j+256]=ll;
}

// E1 = silu(C[pair] ± S[pair] + Xs[src] + Xd[dst] + econst[g] + (±ud)@We1_ud) -> split
__global__ void combine_kernel(const float* __restrict__ We1ud,
                               const float* __restrict__ econst_l)
{
    const int e = blockIdx.x;
    const int g = e / (NPG*DEG), le = e % (NPG*DEG);
    const int i = le / DEG, r = le % DEG;
    const int j = r + (r >= i);
    const int ii = min(i, j), jj = max(i, j);
    const float sgn = (i < j) ? 1.f : -1.f;
    const int pl = ii*DEG - (ii*(ii-1))/2 + (jj - ii - 1);
    const int p = g*NPAIR_G + pl;
    const int sn = g*NPG + i, dn = g*NPG + j;

    const float u0 = sgn * g_ud[p*3+0];
    const float u1 = sgn * g_ud[p*3+1];
    const float u2 = sgn * g_ud[p*3+2];
    const float* Sv = g_S + (size_t)p*HD;
    const float* Cv = g_C + (size_t)p*HD;
    const float* xs = g_Xsd + (size_t)sn*1024;
    const float* xd = g_Xsd + (size_t)dn*1024 + 512;
    const float* ec = econst_l + (size_t)g*HD;
    for (int c = threadIdx.x; c < HD; c += 256) {
        float v = Cv[c] + sgn*Sv[c] + xs[c] + xd[c] + ec[c]
                + u0*We1ud[c] + u1*We1ud[HD+c] + u2*We1ud[2*HD+c];
        v = silu_f(v);
        bf16 h,l; splitf(v,h,l);
        g_E1h[(size_t)e*HD + c] = h;
        g_E1l[(size_t)e*HD + c] = l;
    }
}

// agg[n] = mean over 19 contiguous edges -> cat planes (offset 512, stride 1024)
__global__ void agg_kernel(){
    const int n = blockIdx.x;
    const float* p = g_E2 + (size_t)n*DEG*HD;
    for (int j = threadIdx.x; j < HD; j += 256) {
        float s = 0.f;
        #pragma unroll
        for (int i = 0; i < DEG; i++) s += p[(size_t)i*HD + j];
        s *= (1.f/(float)DEG);
        bf16 h,l; splitf(s,h,l);
        g_cath[(size_t)n*1024 + 512 + j] = h;
        g_catl[(size_t)n*1024 + 512 + j] = l;
    }
}

__global__ void posv_kernel(const float* __restrict__ Wc, float* __restrict__ out){
    const int n = blockIdx.x;
    float a0=0.f, a1=0.f, a2=0.f;
    for (int k = threadIdx.x; k < HD; k += 128) {
        float hv = g_hF[(size_t)n*HD + k];
        a0 += hv*Wc[k*3+0]; a1 += hv*Wc[k*3+1]; a2 += hv*Wc[k*3+2];
    }
    a0 = warp_sum(a0); a1 = warp_sum(a1); a2 = warp_sum(a2);
    __shared__ float sh[4][3];
    int lane = threadIdx.x & 31, w = threadIdx.x >> 5;
    if (lane == 0) { sh[w][0]=a0; sh[w][1]=a1; sh[w][2]=a2; }
    __syncthreads();
    if (threadIdx.x < 3) {
        float s = sh[0][threadIdx.x] + sh[1][threadIdx.x] + sh[2][threadIdx.x] + sh[3][threadIdx.x];
        out[n*3 + threadIdx.x] = s;
    }
}

__global__ void cell_kernel(const int* __restrict__ numat, const float* __restrict__ WL,
                            const float* __restrict__ bL, float* __restrict__ out)
{
    const int b = blockIdx.x;
    const int j = threadIdx.x;
    float cs = 0.f;
    #pragma unroll
    for (int i = 0; i < NPG; i++) cs += g_hF[(size_t)(b*NPG+i)*HD + j];
    float inv_na = 1.f / (float)numat[b];
    float contrib[6];
    #pragma unroll
    for (int c = 0; c < 6; c++)
        contrib[c] = cs * (WL[j*6+c]*inv_na + WL[(HD+j)*6+c]);
    __shared__ float sh[16][6];
    int lane = j & 31, w = j >> 5;
    #pragma unroll
    for (int c = 0; c < 6; c++) {
        float v = warp_sum(contrib[c]);
        if (lane == 0) sh[w][c] = v;
    }
    __syncthreads();
    if (w == 0) {
        #pragma unroll
        for (int c = 0; c < 6; c++) {
            float v = (lane < 16) ? sh[lane][c] : 0.f;
            v = warp_sum(v);
            if (lane == 0) out[b*6 + c] = bL[c] + v;
        }
    }
}

// ---------------- host ----------------
static inline GemmDesc mkdesc(int N, int K,
                              const bf16* Ah, const bf16* Al, int lda,
                              const bf16* Bh, const bf16* Bl, int ldb,
                              float* C, int ldc,
                              const float* bias, const float* res,
                              bf16* Oh, bf16* Ol, int flags){
    GemmDesc d;
    d.Ah=Ah; d.Al=Al; d.Bh=Bh; d.Bl=Bl; d.C=C; d.bias=bias; d.res=res;
    d.Oh=Oh; d.Ol=Ol; d.lda=lda; d.ldb=ldb; d.ldc=ldc; d.K=K; d.nbx=N/128; d.flags=flags;
    return d;
}
static inline void launch_one(int M, const GemmDesc& d){
    int nblk = (M/128) * d.nbx;
    mma_gemm3<<<nblk, 256, SMEM_MMA_BYTES>>>(d, d, d, nblk, nblk);
}

extern "C" void kernel_launch(void* const* d_in, const int* in_sizes, int n_in,
                              void* d_out, int out_size)
{
    const float* t_in   = (const float*)d_in[0];
    const float* fc     = (const float*)d_in[1];
    const float* lp     = (const float*)d_in[2];
    const int*   at     = (const int*)  d_in[3];
    const int*   numat  = (const int*)  d_in[4];
    const int*   n2g    = (const int*)  d_in[5];
    const float* W_node = (const float*)d_in[8];
    const float* W_time = (const float*)d_in[9];
    const float* W_lat  = (const float*)d_in[10];
    const float* ln_g   = (const float*)d_in[11];
    const float* ln_b   = (const float*)d_in[12];
    const float* We1    = (const float*)d_in[13];
    const float* be1    = (const float*)d_in[14];
    const float* We2    = (const float*)d_in[15];
    const float* be2    = (const float*)d_in[16];
    const float* Wn1    = (const float*)d_in[17];
    const float* bn1    = (const float*)d_in[18];
    const float* Wn2    = (const float*)d_in[19];
    const float* bn2    = (const float*)d_in[20];
    const float* Wna    = (const float*)d_in[21];
    const float* flng   = (const float*)d_in[22];
    const float* flnb   = (const float*)d_in[23];
    const float* Wc     = (const float*)d_in[24];
    const float* WL     = (const float*)d_in[25];
    const float* bL     = (const float*)d_in[26];
    float* out = (float*)d_out;
    (void)in_sizes; (void)n_in; (void)out_size;

    cudaFuncSetAttribute(mma_gemm3, cudaFuncAttributeMaxDynamicSharedMemorySize, SMEM_MMA_BYTES);

    #define SYMA(T, var, sym) T* var; { void* p_; cudaGetSymbolAddress(&p_, sym); var = (T*)p_; }
    SYMA(float, bh,   g_h)    SYMA(float, bXsd, g_Xsd)
    SYMA(float, bT1,  g_T1)   SYMA(float, bhF, g_hF)
    SYMA(float, bS,   g_S)    SYMA(float, bC,   g_C)    SYMA(float, bE2, g_E2)
    SYMA(float, bec,  g_econst)
    SYMA(int,   barow,g_arow)
    SYMA(bf16,  sch,  g_sch)  SYMA(bf16, scl,  g_scl)
    SYMA(bf16,  E1h,  g_E1h)  SYMA(bf16, E1l,  g_E1l)
    SYMA(bf16,  cath, g_cath) SYMA(bf16, catl, g_catl)
    SYMA(bf16,  T1h,  g_T1h)  SYMA(bf16, T1l,  g_T1l)
    SYMA(bf16,  Wsdh, g_Wsdh) SYMA(bf16, Wsdl, g_Wsdl)
    SYMA(bf16,  Wfh,  g_Wfh)  SYMA(bf16, Wfl,  g_Wfl)
    SYMA(bf16,  We2h, g_We2h) SYMA(bf16, We2l, g_We2l)
    SYMA(bf16,  Wn1h, g_Wn1h) SYMA(bf16, Wn1l, g_Wn1l)
    SYMA(bf16,  Wn2h, g_Wn2h) SYMA(bf16, Wn2l, g_Wn2l)
    #undef SYMA

    // ---- prologue ----
    atomidx_kernel<<<(NN+255)/256, 256>>>(at);
    lattice_kernel<<<1, 64>>>(lp);
    vtime_kernel<<<(HD+255)/256, 256>>>(W_time, W_lat);
    pair_geom_kernel<<<NP, 384>>>(fc);
    econst_kernel<<<NLAY*NB, HD>>>(We1, be1, Wna, lp, numat);

    // weight packing/splitting
    for (int l = 0; l < NLAY; l++) {
        const float* We1_l = We1 + (size_t)l*EINW*HD;
        pack_sd_kernel<<<(HD*1024)/256, 256>>>(We1_l, Wsdh + (size_t)l*HD*1024, Wsdl + (size_t)l*HD*1024);
        split_kernel<<<(768*HD)/256, 256>>>(We1_l + (size_t)OFF_FEMB*HD, Wfh + (size_t)l*768*HD, Wfl + (size_t)l*768*HD, 768*HD);
    }
    { int n = NLAY*HD*HD;   split_kernel<<<(n+255)/256,256>>>(We2, We2h, We2l, n); }
    { int n = NLAY*2*HD*HD; split_kernel<<<(n+255)/256,256>>>(Wn1, Wn1h, Wn1l, n); }
    { int n = NLAY*HD*HD;   split_kernel<<<(n+255)/256,256>>>(Wn2, Wn2h, Wn2l, n); }

    // h0 = W_node[at-1] @ W_latent[0:512] (+ t*v)
    {
        dim3 g(HD/64, NN/64);
        sgemm2_kernel<64,64,16,4,4><<<g, 256>>>(NN, HD, HD, W_node, HD, W_lat, HD, bh, HD, barow);
    }
    add_tv_kernel<<<NN, HD>>>(t_in, n2g);

    // ---- layers ----
    for (int l = 0; l < NLAY; l++) {
        const float* We1_l = We1 + (size_t)l*EINW*HD;

        ln_kernel<<<NN, 256>>>(bh, ln_g + l*HD, ln_b + l*HD, nullptr, cath, catl, 1024);

        // merged: [Xs|Xd] = hn@[Wsrc|Wdst]  +  S = sin@Ws  +  C = cos@Wc
        {
            GemmDesc dxsd = mkdesc(1024, HD, cath, catl, 1024,
                                   Wsdh + (size_t)l*HD*1024, Wsdl + (size_t)l*HD*1024, 1024,
                                   bXsd, 1024, nullptr, nullptr, nullptr, nullptr, 0);
            GemmDesc dS = mkdesc(HD, 384, sch, scl, 768,
                                 Wfh + (size_t)l*768*HD, Wfl + (size_t)l*768*HD, HD,
                                 bS, HD, nullptr, nullptr, nullptr, nullptr, 0);
            GemmDesc dC = mkdesc(HD, 384, sch + 384, scl + 384, 768,
                                 Wfh + (size_t)l*768*HD + (size_t)384*HD,
                                 Wfl + (size_t)l*768*HD + (size_t)384*HD, HD,
                                 bC, HD, nullptr, nullptr, nullptr, nullptr, 0);
            int n0 = (NN/128) * dxsd.nbx;          // 80
            int n1 = n0 + (NP/128) * dS.nbx;       // 80 + 380
            int nt = n1 + (NP/128) * dC.nbx;       // + 380
            mma_gemm3<<<nt, 256, SMEM_MMA_BYTES>>>(dxsd, dS, dC, n0, n1);
        }

        combine_kernel<<<NE, 256>>>(We1_l + (size_t)OFF_UD*HD, bec + (size_t)l*NB*HD);

        // E2 = silu(E1 @ We2 + be2)
        launch_one(NE, mkdesc(HD, HD, E1h, E1l, HD,
                              We2h + (size_t)l*HD*HD, We2l + (size_t)l*HD*HD, HD,
                              bE2, HD, be2 + l*HD, nullptr, nullptr, nullptr, FLAG_SILU));

        agg_kernel<<<NN, 256>>>();

        // T1 = silu([hn|agg] @ Wn1 + bn1)  (K=1024)
        launch_one(NN, mkdesc(HD, 1024, cath, catl, 1024,
                              Wn1h + (size_t)l*2*HD*HD, Wn1l + (size_t)l*2*HD*HD, HD,
                              bT1, HD, bn1 + l*HD, nullptr, T1h, T1l, FLAG_SILU|FLAG_SPLIT));
        // h = h + silu(T1 @ Wn2 + bn2)
        launch_one(NN, mkdesc(HD, HD, T1h, T1l, HD,
                              Wn2h + (size_t)l*HD*HD, Wn2l + (size_t)l*HD*HD, HD,
                              bh, HD, bn2 + l*HD, bh, nullptr, nullptr, FLAG_SILU));
    }

    // ---- epilogue ----
    ln_kernel<<<NN, 256>>>(bh, flng, flnb, bhF, cath, catl, 1024);
    posv_kernel<<<NN, 128>>>(Wc, out);
    cell_kernel<<<NB, HD>>>(numat, WL, bL, out + NN*3);
}

// round 9
// speedup vs baseline: 1.1287x; 1.1287x over previous
#include <cuda_runtime.h>
#include <cuda_bf16.h>
#include <math.h>
#include <stdint.h>

// ---------------- problem constants ----------------
#define NB    64
#define NPG   20
#define NN    (NB*NPG)          // 1280
#define NE    (NB*NPG*(NPG-1))  // 24320
#define NPAIR_G (NPG*(NPG-1)/2) // 190
#define NP    (NB*NPAIR_G)      // 12160
#define HD    512
#define TDm   256
#define NLAY  6
#define EINW  2313
#define DEG   (NPG-1)           // 19

#define TWO_PI_F 6.2831853071795864f

#define OFF_UD   0
#define OFF_SRC  3
#define OFF_DST  515
#define OFF_LAT  1027
#define OFF_FEMB 1033
#define OFF_NA   1801

#define FLAG_ACC   1
#define FLAG_SILU  2
#define FLAG_SPLIT 4

typedef unsigned long long u64;
typedef __nv_bfloat16 bf16;

// ---------------- scratch (device globals) ----------------
__device__ __align__(16) float g_h   [NN*HD];
__device__ __align__(16) float g_Xsd [NN*1024];   // [Xs | Xd]
__device__ __align__(16) float g_T1  [NN*HD];
__device__ __align__(16) float g_hF  [NN*HD];
__device__ __align__(16) float g_S   [(size_t)NLAY*NP*HD];   // per-layer
__device__ __align__(16) float g_C   [(size_t)NLAY*NP*HD];   // per-layer
__device__ __align__(16) float g_E2  [(size_t)NE*HD];
__device__ __align__(16) float g_ud  [NP*3];
__device__ __align__(16) float g_ltl [NB*9];
__device__ __align__(16) float g_econst[NLAY*NB*HD];
__device__ __align__(16) float g_v   [HD];
__device__ int g_arow[NN];

// bf16 activation planes
__device__ __align__(16) bf16 g_sch [(size_t)NP*768];
__device__ __align__(16) bf16 g_scl [(size_t)NP*768];
__device__ __align__(16) bf16 g_E1h [(size_t)NE*HD];
__device__ __align__(16) bf16 g_E1l [(size_t)NE*HD];
__device__ __align__(16) bf16 g_cath[NN*1024];    // [hn | agg]
__device__ __align__(16) bf16 g_catl[NN*1024];
__device__ __align__(16) bf16 g_T1h [NN*HD];
__device__ __align__(16) bf16 g_T1l [NN*HD];

// bf16 weight planes (K-major as in source)
__device__ __align__(16) bf16 g_Wsdh[(size_t)NLAY*HD*1024];  // [Wsrc|Wdst] packed
__device__ __align__(16) bf16 g_Wsdl[(size_t)NLAY*HD*1024];
__device__ __align__(16) bf16 g_Wfh [(size_t)NLAY*768*HD];
__device__ __align__(16) bf16 g_Wfl [(size_t)NLAY*768*HD];
__device__ __align__(16) bf16 g_We2h[(size_t)NLAY*HD*HD];
__device__ __align__(16) bf16 g_We2l[(size_t)NLAY*HD*HD];
__device__ __align__(16) bf16 g_Wn1h[(size_t)NLAY*2*HD*HD];
__device__ __align__(16) bf16 g_Wn1l[(size_t)NLAY*2*HD*HD];
__device__ __align__(16) bf16 g_Wn2h[(size_t)NLAY*HD*HD];
__device__ __align__(16) bf16 g_Wn2l[(size_t)NLAY*HD*HD];

// ---------------- helpers ----------------
__device__ __forceinline__ float warp_sum(float v){
    #pragma unroll
    for (int o = 16; o > 0; o >>= 1) v += __shfl_down_sync(0xffffffffu, v, o);
    return v;
}
__device__ __forceinline__ float silu_f(float v){ return v / (1.f + expf(-v)); }
__device__ __forceinline__ void splitf(float v, bf16 &h, bf16 &l){
    h = __float2bfloat16(v);
    l = __float2bfloat16(v - __bfloat162float(h));
}
__device__ __forceinline__ uint32_t sm_u32(const void* p){
    return (uint32_t)__cvta_generic_to_shared(p);
}
__device__ __forceinline__ void ldsm_x4(uint32_t &r0, uint32_t &r1, uint32_t &r2, uint32_t &r3, uint32_t a){
    asm volatile("ldmatrix.sync.aligned.m8n8.x4.shared.b16 {%0,%1,%2,%3}, [%4];"
        : "=r"(r0),"=r"(r1),"=r"(r2),"=r"(r3) : "r"(a));
}
__device__ __forceinline__ void ldsm_x4t(uint32_t &r0, uint32_t &r1, uint32_t &r2, uint32_t &r3, uint32_t a){
    asm volatile("ldmatrix.sync.aligned.m8n8.x4.trans.shared.b16 {%0,%1,%2,%3}, [%4];"
        : "=r"(r0),"=r"(r1),"=r"(r2),"=r"(r3) : "r"(a));
}
__device__ __forceinline__ void mma_bf16(float* c, const uint32_t* a, const uint32_t* b){
    asm volatile(
      "mma.sync.aligned.m16n8k16.row.col.f32.bf16.bf16.f32 "
      "{%0,%1,%2,%3}, {%4,%5,%6,%7}, {%8,%9}, {%0,%1,%2,%3};"
      : "+f"(c[0]),"+f"(c[1]),"+f"(c[2]),"+f"(c[3])
      : "r"(a[0]),"r"(a[1]),"r"(a[2]),"r"(a[3]), "r"(b[0]),"r"(b[1]));
}
__device__ __forceinline__ void cp16(uint32_t s, const void* g){
    asm volatile("cp.async.cg.shared.global [%0], [%1], 16;" :: "r"(s), "l"(g));
}
#define CP_COMMIT() asm volatile("cp.async.commit_group;" ::: "memory")
template<int N> __device__ __forceinline__ void cp_wait(){
    asm volatile("cp.async.wait_group %0;" :: "n"(N) : "memory");
}

// ---------------- split-bf16 tensor-core GEMM (R7-proven 2-stage body) --------------
// C = (Ah+Al) @ (Bh+Bl): AhBh + AhBl + AlBh, fp32 accumulate.
// Block 256 threads, tile 128x128, K-chunk 32, 2-stage cp.async (3 CTAs/SM).
// Stage layout (bf16 elems): Ah[128][40] @0, Al @5120, Bh[32][136] @10240, Bl @14592.
#define STG_ELEMS 18944
#define SMEM_MMA_BYTES (2*STG_ELEMS*2)

__device__ __forceinline__ void mm_load_stage(bf16* st, int tid,
    const bf16* __restrict__ Ah, const bf16* __restrict__ Al,
    const bf16* __restrict__ Bh, const bf16* __restrict__ Bl,
    int row0, int col0, int lda, int ldb, int k0)
{
    #pragma unroll
    for (int t = 0; t < 2; t++) {
        int lin = tid + t*256;
        int r = lin >> 2, c8 = (lin & 3) * 8;
        cp16(sm_u32(st +          r*40 + c8), Ah + (size_t)(row0+r)*lda + k0 + c8);
        cp16(sm_u32(st +  5120 +  r*40 + c8), Al + (size_t)(row0+r)*lda + k0 + c8);
        int rb = lin >> 4, cb = (lin & 15) * 8;
        cp16(sm_u32(st + 10240 + rb*136 + cb), Bh + (size_t)(k0+rb)*ldb + col0 + cb);
        cp16(sm_u32(st + 14592 + rb*136 + cb), Bl + (size_t)(k0+rb)*ldb + col0 + cb);
    }
    CP_COMMIT();
}

__device__ __forceinline__ void mm_compute_stage(const bf16* st, float acc[4][4][4],
                                                 int wm, int wn, int lane)
{
    const bf16* ah_ = st;
    const bf16* al_ = st + 5120;
    const bf16* bh_ = st + 10240;
    const bf16* bl_ = st + 14592;
    #pragma unroll
    for (int ks = 0; ks < 32; ks += 16) {
        uint32_t ah[4][4], al[4][4], bh[4][2], bl[4][2];
        #pragma unroll
        for (int mt = 0; mt < 4; mt++) {
            int rr = wm + mt*16 + (lane & 15);
            int cc = ks + (lane >> 4)*8;
            ldsm_x4(ah[mt][0],ah[mt][1],ah[mt][2],ah[mt][3], sm_u32(ah_ + rr*40 + cc));
            ldsm_x4(al[mt][0],al[mt][1],al[mt][2],al[mt][3], sm_u32(al_ + rr*40 + cc));
        }
        #pragma unroll
        for (int nt2 = 0; nt2 < 2; nt2++) {
            int rr = ks + (lane & 15);
            int cc = wn + nt2*16 + (lane >> 4)*8;
            uint32_t r0,r1,r2,r3;
            ldsm_x4t(r0,r1,r2,r3, sm_u32(bh_ + rr*136 + cc));
            bh[nt2*2][0]=r0; bh[nt2*2][1]=r1; bh[nt2*2+1][0]=r2; bh[nt2*2+1][1]=r3;
            ldsm_x4t(r0,r1,r2,r3, sm_u32(bl_ + rr*136 + cc));
            bl[nt2*2][0]=r0; bl[nt2*2][1]=r1; bl[nt2*2+1][0]=r2; bl[nt2*2+1][1]=r3;
        }
        #pragma unroll
        for (int mt = 0; mt < 4; mt++)
            #pragma unroll
            for (int nt = 0; nt < 4; nt++) {
                mma_bf16(acc[mt][nt], ah[mt], bh[nt]);
                mma_bf16(acc[mt][nt], ah[mt], bl[nt]);
                mma_bf16(acc[mt][nt], al[mt], bh[nt]);
            }
    }
}

__device__ __forceinline__ void gemm_body(int K,
    const bf16* __restrict__ Ah, const bf16* __restrict__ Al, int lda,
    const bf16* __restrict__ Bh, const bf16* __restrict__ Bl, int ldb,
    float* __restrict__ C, int ldc,
    const float* __restrict__ bias, const float* __restrict__ residual,
    bf16* __restrict__ Oh, bf16* __restrict__ Ol,
    int flags, int row0, int col0, char* dsmem)
{
    bf16* st0 = (bf16*)dsmem;
    bf16* st1 = st0 + STG_ELEMS;

    const int tid  = threadIdx.x;
    const int warp = tid >> 5, lane = tid & 31;
    const int wm = (warp >> 2) * 64;
    const int wn = (warp & 3) * 32;

    float acc[4][4][4];
    #pragma unroll
    for (int i = 0; i < 4; i++)
        #pragma unroll
        for (int j = 0; j < 4; j++)
            #pragma unroll
            for (int k = 0; k < 4; k++) acc[i][j][k] = 0.f;

    const int nch = K >> 5;
    mm_load_stage(st0, tid, Ah, Al, Bh, Bl, row0, col0, lda, ldb, 0);
    for (int kc = 0; kc < nch; kc++) {
        bf16* cur = (kc & 1) ? st1 : st0;
        bf16* nxt = (kc & 1) ? st0 : st1;
        if (kc + 1 < nch) {
            mm_load_stage(nxt, tid, Ah, Al, Bh, Bl, row0, col0, lda, ldb, (kc+1)*32);
            cp_wait<1>();
        } else {
            cp_wait<0>();
        }
        __syncthreads();
        mm_compute_stage(cur, acc, wm, wn, lane);
        __syncthreads();
    }

    #pragma unroll
    for (int mt = 0; mt < 4; mt++) {
        #pragma unroll
        for (int nt = 0; nt < 4; nt++) {
            #pragma unroll
            for (int half = 0; half < 2; half++) {
                int rr = row0 + wm + mt*16 + (lane >> 2) + half*8;
                int cc = col0 + wn + nt*8 + (lane & 3)*2;
                float v0 = acc[mt][nt][half*2 + 0];
                float v1 = acc[mt][nt][half*2 + 1];
                size_t o = (size_t)rr*ldc + cc;
                if (flags & FLAG_ACC)  { v0 += C[o]; v1 += C[o+1]; }
                if (bias)              { v0 += bias[cc]; v1 += bias[cc+1]; }
                if (flags & FLAG_SILU) { v0 = silu_f(v0); v1 = silu_f(v1); }
                if (residual)          { v0 += residual[o]; v1 += residual[o+1]; }
                *(float2*)(C + o) = make_float2(v0, v1);
                if (flags & FLAG_SPLIT) {
                    bf16 h0,l0,h1,l1;
                    splitf(v0,h0,l0); splitf(v1,h1,l1);
                    *(__nv_bfloat162*)(Oh + o) = __nv_bfloat162(h0, h1);
                    *(__nv_bfloat162*)(Ol + o) = __nv_bfloat162(l0, l1);
                }
            }
        }
    }
}

// general GEMM: grid (N/128, M/128)
__global__ __launch_bounds__(256)
void mma_gemm(int K,
    const bf16* __restrict__ Ah, const bf16* __restrict__ Al, int lda,
    const bf16* __restrict__ Bh, const bf16* __restrict__ Bl, int ldb,
    float* __restrict__ C, int ldc,
    const float* __restrict__ bias, const float* __restrict__ residual,
    bf16* __restrict__ Oh, bf16* __restrict__ Ol,
    int flags)
{
    extern __shared__ __align__(16) char dsmem[];
    gemm_body(K, Ah, Al, lda, Bh, Bl, ldb, C, ldc, bias, residual, Oh, Ol, flags,
              blockIdx.y*128, blockIdx.x*128, dsmem);
}

// all-layer femb GEMM: 4560 blocks = NLAY(6) * half(2:S,C) * (NP/128=95) * (HD/128=4)
__global__ __launch_bounds__(256)
void mma_gemm_femb(const bf16* __restrict__ sch, const bf16* __restrict__ scl,
                   const bf16* __restrict__ Wfh, const bf16* __restrict__ Wfl,
                   float* __restrict__ S, float* __restrict__ Cc)
{
    extern __shared__ __align__(16) char dsmem[];
    int bi = blockIdx.x;
    const int PER_L = 2*(NP/128)*(HD/128);      // 760
    int l = bi / PER_L, r = bi % PER_L;
    int half = r / ((NP/128)*(HD/128));
    int t = r % ((NP/128)*(HD/128));
    int row0 = (t / (HD/128)) * 128;
    int col0 = (t % (HD/128)) * 128;
    const bf16* Ah = sch + half*384;
    const bf16* Al = scl + half*384;
    const bf16* Bh = Wfh + (size_t)l*768*HD + (size_t)half*384*HD;
    const bf16* Bl = Wfl + (size_t)l*768*HD + (size_t)half*384*HD;
    float* C = (half ? Cc : S) + (size_t)l*NP*HD;
    gemm_body(384, Ah, Al, 768, Bh, Bl, HD, C, HD,
              nullptr, nullptr, nullptr, nullptr, 0, row0, col0, dsmem);
}

// ---------------- FFMA2 SGEMM (prologue h0 only) ----
__device__ __forceinline__ u64 pack2(float x, float y){
    u64 r; asm("mov.b64 %0, {%1, %2};" : "=l"(r) : "f"(x), "f"(y)); return r;
}
__device__ __forceinline__ void unpack2(u64 v, float &x, float &y){
    asm("mov.b64 {%0, %1}, %2;" : "=f"(x), "=f"(y) : "l"(v));
}
__device__ __forceinline__ void ffma2(u64 &acc, u64 a, u64 b){
    asm("fma.rn.f32x2 %0, %1, %2, %0;" : "+l"(acc) : "l"(a), "l"(b));
}
template<int BM,int BN,int BK,int TM,int TN>
__global__ __launch_bounds__((BM/TM)*(BN/TN))
void sgemm2_kernel(int M, int N, int K,
                   const float* __restrict__ A, int lda,
                   const float* __restrict__ B, int ldb,
                   float* __restrict__ C, int ldc,
                   const int* __restrict__ arow)
{
    __shared__ __align__(16) float As[BK][BM];
    __shared__ __align__(16) float Bs[BK][BN];
    const int tid = threadIdx.x;
    const int tx  = tid % (BN/TN);
    const int ty  = tid / (BN/TN);
    const int row0 = blockIdx.y * BM;
    const int col0 = blockIdx.x * BN;
    constexpr int AVPR = BK/4;
    const int a_r = tid / AVPR;
    const int a_c = (tid % AVPR) * 4;
    constexpr int BVPR = BN/4;
    const int b_r = tid / BVPR;
    const int b_c = (tid % BVPR) * 4;
    const float* Arow = A + (size_t)(arow ? arow[row0 + a_r] : (row0 + a_r)) * lda;

    u64 acc[TM][TN/2];
    #pragma unroll
    for (int i = 0; i < TM; i++)
        #pragma unroll
        for (int j = 0; j < TN/2; j++) acc[i][j] = 0ull;

    for (int k0 = 0; k0 < K; k0 += BK) {
        float4 av = *(const float4*)(Arow + k0 + a_c);
        As[a_c+0][a_r] = av.x; As[a_c+1][a_r] = av.y;
        As[a_c+2][a_r] = av.z; As[a_c+3][a_r] = av.w;
        *(float4*)&Bs[b_r][b_c] = *(const float4*)(B + (size_t)(k0 + b_r)*ldb + col0 + b_c);
        __syncthreads();
        #pragma unroll
        for (int kk = 0; kk < BK; kk++) {
            float a[TM];
            #pragma unroll
            for (int i = 0; i < TM; i += 4) {
                float4 t = *(const float4*)&As[kk][ty*TM + i];
                a[i]=t.x; a[i+1]=t.y; a[i+2]=t.z; a[i+3]=t.w;
            }
            u64 ap[TM];
            #pragma unroll
            for (int i = 0; i < TM; i++) ap[i] = pack2(a[i], a[i]);
            u64 bp[TN/2];
            #pragma unroll
            for (int j = 0; j < TN/2; j += 2) {
                ulonglong2 t = *(const ulonglong2*)&Bs[kk][tx*TN + 2*j];
                bp[j] = t.x; bp[j+1] = t.y;
            }
            #pragma unroll
            for (int i = 0; i < TM; i++)
                #pragma unroll
                for (int j = 0; j < TN/2; j++)
                    ffma2(acc[i][j], ap[i], bp[j]);
        }
        __syncthreads();
    }
    #pragma unroll
    for (int i = 0; i < TM; i++) {
        const int r = row0 + ty*TM + i;
        #pragma unroll
        for (int j = 0; j < TN/2; j++) {
            const int c = col0 + tx*TN + 2*j;
            float v0, v1; unpack2(acc[i][j], v0, v1);
            C[(size_t)r*ldc + c]   = v0;
            C[(size_t)r*ldc + c+1] = v1;
        }
    }
}

// ---------------- glue kernels ----------------
__global__ void split_kernel(const float* __restrict__ in, bf16* __restrict__ oh,
                             bf16* __restrict__ ol, int n){
    int i = blockIdx.x*256 + threadIdx.x;
    if (i < n) { bf16 h,l; splitf(in[i], h, l); oh[i]=h; ol[i]=l; }
}

// all-layer pack [Wsrc | Wdst] (NLAY x 512 x 1024) and split
__global__ void pack_sd_kernel(const float* __restrict__ We1,
                               bf16* __restrict__ oh, bf16* __restrict__ ol){
    int idx = blockIdx.x*256 + threadIdx.x;   // NLAY*512*1024 total
    int l = idx >> 19;                         // / (512*1024)
    int rem = idx & ((512*1024)-1);
    int k = rem >> 10, c = rem & 1023;
    const float* W = We1 + (size_t)l*EINW*HD;
    float v = (c < 512) ? W[(size_t)(OFF_SRC + k)*HD + c]
                        : W[(size_t)(OFF_DST + k)*HD + (c - 512)];
    bf16 h,l2; splitf(v,h,l2);
    oh[idx]=h; ol[idx]=l2;
}

// all-layer femb weight split (strided gather from We1 slabs)
__global__ void split_femb_kernel(const float* __restrict__ We1,
                                  bf16* __restrict__ oh, bf16* __restrict__ ol){
    int idx = blockIdx.x*256 + threadIdx.x;   // NLAY*768*HD total
    int l = idx / (768*HD);
    int rem = idx - l*(768*HD);
    float v = We1[(size_t)l*EINW*HD + (size_t)OFF_FEMB*HD + rem];
    bf16 h,l2; splitf(v,h,l2);
    oh[idx]=h; ol[idx]=l2;
}

__global__ void atomidx_kernel(const int* __restrict__ at){
    int n = blockIdx.x*256 + threadIdx.x;
    if (n < NN) g_arow[n] = max(at[n]-1, 0);
}

__global__ void vtime_kernel(const float* __restrict__ Wt, const float* __restrict__ Wl){
    int j = blockIdx.x*256 + threadIdx.x;
    if (j >= HD) return;
    float acc = 0.f;
    for (int k = 0; k < TDm; k++) acc += Wt[k] * Wl[(size_t)(HD + k)*HD + j];
    g_v[j] = acc;
}

__global__ void add_tv_kernel(const float* __restrict__ t, const int* __restrict__ n2g){
    int n = blockIdx.x; int j = threadIdx.x;
    g_h[(size_t)n*HD + j] += t[n2g[n]] * g_v[j];
}

__global__ void lattice_kernel(const float* __restrict__ lp){
    int b = blockIdx.x*64 + threadIdx.x;
    if (b >= NB) return;
    const float LM[3] = {1.575442910194397f, 1.7017393112182617f, 1.9781638383865356f};
    const float LS[3] = {0.24437622725963593f, 0.26526379585266113f, 0.3535512685775757f};
    float len[3], ang[3];
    #pragma unroll
    for (int i = 0; i < 3; i++) {
        len[i] = expf(lp[b*6+i]*LS[i] + LM[i]);
        float x = lp[b*6+3+i];
        float sg = 1.f/(1.f+expf(-x));
        ang[i] = (59.9f + 60.2f*sg) * (3.14159265358979323846f/180.f);
    }
    float c0=cosf(ang[0]), c1=cosf(ang[1]), c2=cosf(ang[2]);
    float s0=sinf(ang[0]), s1=sinf(ang[1]);
    float val = (c0*c1 - c2) / (s0*s1);
    val = fminf(1.f, fmaxf(-1.f, val));
    float gs = acosf(val);
    float L[3][3];
    L[0][0]=len[0]*s1;            L[0][1]=0.f;                 L[0][2]=len[0]*c1;
    L[1][0]=-len[1]*s0*cosf(gs);  L[1][1]=len[1]*s0*sinf(gs);  L[1][2]=len[1]*c0;
    L[2][0]=0.f;                  L[2][1]=0.f;                 L[2][2]=len[2];
    #pragma unroll
    for (int i = 0; i < 3; i++)
        #pragma unroll
        for (int k = 0; k < 3; k++)
            g_ltl[b*9 + i*3 + k] = L[i][0]*L[k][0] + L[i][1]*L[k][1] + L[i][2]*L[k][2];
}

__global__ void pair_geom_kernel(const float* __restrict__ fc)
{
    const int p = blockIdx.x;
    __shared__ float d[3];
    if (threadIdx.x == 0) {
        int g = p / NPAIR_G, q = p % NPAIR_G;
        int i = 0, base = 0;
        while (base + (DEG - i) <= q) { base += DEG - i; i++; }
        int j = i + 1 + (q - base);
        int ni = g*NPG + i, nj = g*NPG + j;
        float dd[3];
        #pragma unroll
        for (int k = 0; k < 3; k++) {
            float z = TWO_PI_F * (fc[nj*3+k] - fc[ni*3+k]);
            dd[k] = atan2f(sinf(z), cosf(z)) * (1.f/TWO_PI_F);
        }
        float dot[3];
        #pragma unroll
        for (int k = 0; k < 3; k++)
            dot[k] = g_ltl[g*9+k*3+0]*dd[0] + g_ltl[g*9+k*3+1]*dd[1] + g_ltl[g*9+k*3+2]*dd[2];
        float nrm = sqrtf(dot[0]*dot[0] + dot[1]*dot[1] + dot[2]*dot[2]) + 1e-12f;
        #pragma unroll
        for (int k = 0; k < 3; k++) {
            g_ud[p*3+k] = dot[k] / nrm;
            d[k] = dd[k];
        }
    }
    __syncthreads();
    int idx = threadIdx.x;          // 384 threads
    int dim = idx >> 7, k = idx & 127;
    float ang = d[dim] * (TWO_PI_F * (float)k);
    float s, c; sincosf(ang, &s, &c);
    bf16 h,l;
    splitf(s,h,l);
    g_sch[(size_t)p*768 + idx] = h; g_scl[(size_t)p*768 + idx] = l;
    splitf(c,h,l);
    g_sch[(size_t)p*768 + 384 + idx] = h; g_scl[(size_t)p*768 + 384 + idx] = l;
}

__global__ void econst_kernel(const float* __restrict__ We1, const float* __restrict__ be1,
                              const float* __restrict__ Wna, const float* __restrict__ lp,
                              const int* __restrict__ numat)
{
    const int l = blockIdx.x / NB, b = blockIdx.x % NB;
    const int j = threadIdx.x;
    const float* W = We1 + (size_t)l*EINW*HD;
    float acc = be1[l*HD + j];
    #pragma unroll
    for (int k = 0; k < 6; k++)
        acc += lp[b*6+k] * W[(size_t)(OFF_LAT+k)*HD + j];
    const float* na = Wna + (size_t)l*100*HD + (size_t)max(numat[b]-1,0)*HD;
    for (int k = 0; k < HD; k++)
        acc += na[k] * W[(size_t)(OFF_NA+k)*HD + j];
    g_econst[((size_t)l*NB + b)*HD + j] = acc;
}

// LayerNorm; optional fp32 out (stride HD) + bf16 planes (stride ldp)
__global__ void ln_kernel(const float* __restrict__ x, const float* __restrict__ g,
                          const float* __restrict__ b, float* __restrict__ y,
                          bf16* __restrict__ yh, bf16* __restrict__ yl, int ldp)
{
    const int n = blockIdx.x;
    const int j = threadIdx.x;
    const float* xr = x + (size_t)n*HD;
    float v0 = xr[j], v1 = xr[j+256];
    __shared__ float sh[8];
    int lane = j & 31, w = j >> 5;
    float s = warp_sum(v0 + v1);
    if (lane == 0) sh[w] = s;
    __syncthreads();
    if (w == 0) { float t = (lane < 8) ? sh[lane] : 0.f; t = warp_sum(t); if (lane==0) sh[0]=t; }
    __syncthreads();
    float mean = sh[0] * (1.f/HD);
    __syncthreads();
    float d0 = v0 - mean, d1 = v1 - mean;
    float q = warp_sum(d0*d0 + d1*d1);
    if (lane == 0) sh[w] = q;
    __syncthreads();
    if (w == 0) { float t = (lane < 8) ? sh[lane] : 0.f; t = warp_sum(t); if (lane==0) sh[0]=t; }
    __syncthreads();
    float inv = rsqrtf(sh[0]*(1.f/HD) + 1e-5f);
    float o0 = d0*inv*g[j]     + b[j];
    float o1 = d1*inv*g[j+256] + b[j+256];
    if (y) {
        y[(size_t)n*HD + j]     = o0;
        y[(size_t)n*HD + j+256] = o1;
    }
    bf16 hh,ll;
    splitf(o0,hh,ll); yh[(size_t)n*ldp+j]=hh;     yl[(size_t)n*ldp+j]=ll;
    splitf(o1,hh,ll); yh[(size_t)n*ldp+j+256]=hh; yl[(size_t)n*ldp+j+256]=ll;
}

// E1 = silu(C[pair] ± S[pair] + Xs[src] + Xd[dst] + econst[g] + (±ud)@We1_ud) -> split
__global__ void combine_kernel(const float* __restrict__ We1ud,
                               const float* __restrict__ econst_l,
                               const float* __restrict__ Sl,
                               const float* __restrict__ Cl)
{
    const int e = blockIdx.x;
    const int g = e / (NPG*DEG), le = e % (NPG*DEG);
    const int i = le / DEG, r = le % DEG;
    const int j = r + (r >= i);
    const int ii = min(i, j), jj = max(i, j);
    const float sgn = (i < j) ? 1.f : -1.f;
    const int pl = ii*DEG - (ii*(ii-1))/2 + (jj - ii - 1);
    const int p = g*NPAIR_G + pl;
    const int sn = g*NPG + i, dn = g*NPG + j;

    const float u0 = sgn * g_ud[p*3+0];
    const float u1 = sgn * g_ud[p*3+1];
    const float u2 = sgn * g_ud[p*3+2];
    const float* Sv = Sl + (size_t)p*HD;
    const float* Cv = Cl + (size_t)p*HD;
    const float* xs = g_Xsd + (size_t)sn*1024;
    const float* xd = g_Xsd + (size_t)dn*1024 + 512;
    const float* ec = econst_l + (size_t)g*HD;
    for (int c = threadIdx.x; c < HD; c += 256) {
        float v = Cv[c] + sgn*Sv[c] + xs[c] + xd[c] + ec[c]
                + u0*We1ud[c] + u1*We1ud[HD+c] + u2*We1ud[2*HD+c];
        v = silu_f(v);
        bf16 h,l; splitf(v,h,l);
        g_E1h[(size_t)e*HD + c] = h;
        g_E1l[(size_t)e*HD + c] = l;
    }
}

// agg[n] = mean over 19 contiguous edges -> cat planes (offset 512, stride 1024)
__global__ void agg_kernel(){
    const int n = blockIdx.x;
    const float* p = g_E2 + (size_t)n*DEG*HD;
    for (int j = threadIdx.x; j < HD; j += 256) {
        float s = 0.f;
        #pragma unroll
        for (int i = 0; i < DEG; i++) s += p[(size_t)i*HD + j];
        s *= (1.f/(float)DEG);
        bf16 h,l; splitf(s,h,l);
        g_cath[(size_t)n*1024 + 512 + j] = h;
        g_catl[(size_t)n*1024 + 512 + j] = l;
    }
}

__global__ void posv_kernel(const float* __restrict__ Wc, float* __restrict__ out){
    const int n = blockIdx.x;
    float a0=0.f, a1=0.f, a2=0.f;
    for (int k = threadIdx.x; k < HD; k += 128) {
        float hv = g_hF[(size_t)n*HD + k];
        a0 += hv*Wc[k*3+0]; a1 += hv*Wc[k*3+1]; a2 += hv*Wc[k*3+2];
    }
    a0 = warp_sum(a0); a1 = warp_sum(a1); a2 = warp_sum(a2);
    __shared__ float sh[4][3];
    int lane = threadIdx.x & 31, w = threadIdx.x >> 5;
    if (lane == 0) { sh[w][0]=a0; sh[w][1]=a1; sh[w][2]=a2; }
    __syncthreads();
    if (threadIdx.x < 3) {
        float s = sh[0][threadIdx.x] + sh[1][threadIdx.x] + sh[2][threadIdx.x] + sh[3][threadIdx.x];
        out[n*3 + threadIdx.x] = s;
    }
}

__global__ void cell_kernel(const int* __restrict__ numat, const float* __restrict__ WL,
                            const float* __restrict__ bL, float* __restrict__ out)
{
    const int b = blockIdx.x;
    const int j = threadIdx.x;
    float cs = 0.f;
    #pragma unroll
    for (int i = 0; i < NPG; i++) cs += g_hF[(size_t)(b*NPG+i)*HD + j];
    float inv_na = 1.f / (float)numat[b];
    float contrib[6];
    #pragma unroll
    for (int c = 0; c < 6; c++)
        contrib[c] = cs * (WL[j*6+c]*inv_na + WL[(HD+j)*6+c]);
    __shared__ float sh[16][6];
    int lane = j & 31, w = j >> 5;
    #pragma unroll
    for (int c = 0; c < 6; c++) {
        float v = warp_sum(contrib[c]);
        if (lane == 0) sh[w][c] = v;
    }
    __syncthreads();
    if (w == 0) {
        #pragma unroll
        for (int c = 0; c < 6; c++) {
            float v = (lane < 16) ? sh[lane][c] : 0.f;
            v = warp_sum(v);
            if (lane == 0) out[b*6 + c] = bL[c] + v;
        }
    }
}

// ---------------- host ----------------
static inline void launch_mma(int M, int N, int K,
                              const bf16* Ah, const bf16* Al, int lda,
                              const bf16* Bh, const bf16* Bl, int ldb,
                              float* C, int ldc,
                              const float* bias, const float* res,
                              bf16* Oh, bf16* Ol, int flags){
    dim3 g(N/128, M/128);
    mma_gemm<<<g, 256, SMEM_MMA_BYTES>>>(K, Ah, Al, lda, Bh, Bl, ldb, C, ldc, bias, res, Oh, Ol, flags);
}

extern "C" void kernel_launch(void* const* d_in, const int* in_sizes, int n_in,
                              void* d_out, int out_size)
{
    const float* t_in   = (const float*)d_in[0];
    const float* fc     = (const float*)d_in[1];
    const float* lp     = (const float*)d_in[2];
    const int*   at     = (const int*)  d_in[3];
    const int*   numat  = (const int*)  d_in[4];
    const int*   n2g    = (const int*)  d_in[5];
    const float* W_node = (const float*)d_in[8];
    const float* W_time = (const float*)d_in[9];
    const float* W_lat  = (const float*)d_in[10];
    const float* ln_g   = (const float*)d_in[11];
    const float* ln_b   = (const float*)d_in[12];
    const float* We1    = (const float*)d_in[13];
    const float* be1    = (const float*)d_in[14];
    const float* We2    = (const float*)d_in[15];
    const float* be2    = (const float*)d_in[16];
    const float* Wn1    = (const float*)d_in[17];
    const float* bn1    = (const float*)d_in[18];
    const float* Wn2    = (const float*)d_in[19];
    const float* bn2    = (const float*)d_in[20];
    const float* Wna    = (const float*)d_in[21];
    const float* flng   = (const float*)d_in[22];
    const float* flnb   = (const float*)d_in[23];
    const float* Wc     = (const float*)d_in[24];
    const float* WL     = (const float*)d_in[25];
    const float* bL     = (const float*)d_in[26];
    float* out = (float*)d_out;
    (void)in_sizes; (void)n_in; (void)out_size;

    cudaFuncSetAttribute(mma_gemm, cudaFuncAttributeMaxDynamicSharedMemorySize, SMEM_MMA_BYTES);
    cudaFuncSetAttribute(mma_gemm_femb, cudaFuncAttributeMaxDynamicSharedMemorySize, SMEM_MMA_BYTES);

    #define SYMA(T, var, sym) T* var; { void* p_; cudaGetSymbolAddress(&p_, sym); var = (T*)p_; }
    SYMA(float, bh,   g_h)    SYMA(float, bXsd, g_Xsd)
    SYMA(float, bT1,  g_T1)   SYMA(float, bhF, g_hF)
    SYMA(float, bS,   g_S)    SYMA(float, bC,   g_C)    SYMA(float, bE2, g_E2)
    SYMA(float, bec,  g_econst)
    SYMA(int,   barow,g_arow)
    SYMA(bf16,  sch,  g_sch)  SYMA(bf16, scl,  g_scl)
    SYMA(bf16,  E1h,  g_E1h)  SYMA(bf16, E1l,  g_E1l)
    SYMA(bf16,  cath, g_cath) SYMA(bf16, catl, g_catl)
    SYMA(bf16,  T1h,  g_T1h)  SYMA(bf16, T1l,  g_T1l)
    SYMA(bf16,  Wsdh, g_Wsdh) SYMA(bf16, Wsdl, g_Wsdl)
    SYMA(bf16,  Wfh,  g_Wfh)  SYMA(bf16, Wfl,  g_Wfl)
    SYMA(bf16,  We2h, g_We2h) SYMA(bf16, We2l, g_We2l)
    SYMA(bf16,  Wn1h, g_Wn1h) SYMA(bf16, Wn1l, g_Wn1l)
    SYMA(bf16,  Wn2h, g_Wn2h) SYMA(bf16, Wn2l, g_Wn2l)
    #undef SYMA

    // ---- prologue ----
    atomidx_kernel<<<(NN+255)/256, 256>>>(at);
    lattice_kernel<<<1, 64>>>(lp);
    vtime_kernel<<<(HD+255)/256, 256>>>(W_time, W_lat);
    pair_geom_kernel<<<NP, 384>>>(fc);
    econst_kernel<<<NLAY*NB, HD>>>(We1, be1, Wna, lp, numat);

    // weight packing/splitting (all layers, consolidated launches)
    pack_sd_kernel<<<(NLAY*HD*1024)/256, 256>>>(We1, Wsdh, Wsdl);
    split_femb_kernel<<<(NLAY*768*HD)/256, 256>>>(We1, Wfh, Wfl);
    { int n = NLAY*HD*HD;   split_kernel<<<(n+255)/256,256>>>(We2, We2h, We2l, n); }
    { int n = NLAY*2*HD*HD; split_kernel<<<(n+255)/256,256>>>(Wn1, Wn1h, Wn1l, n); }
    { int n = NLAY*HD*HD;   split_kernel<<<(n+255)/256,256>>>(Wn2, Wn2h, Wn2l, n); }

    // all-layer femb GEMMs: S[l], C[l] for l = 0..5 in one launch (4560 blocks)
    mma_gemm_femb<<<NLAY*2*(NP/128)*(HD/128), 256, SMEM_MMA_BYTES>>>(sch, scl, Wfh, Wfl, bS, bC);

    // h0 = W_node[at-1] @ W_latent[0:512] (+ t*v)
    {
        dim3 g(HD/64, NN/64);
        sgemm2_kernel<64,64,16,4,4><<<g, 256>>>(NN, HD, HD, W_node, HD, W_lat, HD, bh, HD, barow);
    }
    add_tv_kernel<<<NN, HD>>>(t_in, n2g);

    // ---- layers ----
    for (int l = 0; l < NLAY; l++) {
        const float* We1_l = We1 + (size_t)l*EINW*HD;

        ln_kernel<<<NN, 256>>>(bh, ln_g + l*HD, ln_b + l*HD, nullptr, cath, catl, 1024);

        // [Xs|Xd] = hn @ [Wsrc|Wdst]
        launch_mma(NN, 1024, HD, cath, catl, 1024,
                   Wsdh + (size_t)l*HD*1024, Wsdl + (size_t)l*HD*1024, 1024,
                   bXsd, 1024, nullptr, nullptr, nullptr, nullptr, 0);

        combine_kernel<<<NE, 256>>>(We1_l + (size_t)OFF_UD*HD, bec + (size_t)l*NB*HD,
                                    bS + (size_t)l*NP*HD, bC + (size_t)l*NP*HD);

        // E2 = silu(E1 @ We2 + be2)
        launch_mma(NE, HD, HD, E1h, E1l, HD,
                   We2h + (size_t)l*HD*HD, We2l + (size_t)l*HD*HD, HD,
                   bE2, HD, be2 + l*HD, nullptr, nullptr, nullptr, FLAG_SILU);

        agg_kernel<<<NN, 256>>>();

        // T1 = silu([hn|agg] @ Wn1 + bn1)  (K=1024)
        launch_mma(NN, HD, 1024, cath, catl, 1024,
                   Wn1h + (size_t)l*2*HD*HD, Wn1l + (size_t)l*2*HD*HD, HD,
                   bT1, HD, bn1 + l*HD, nullptr, T1h, T1l, FLAG_SILU|FLAG_SPLIT);
        // h = h + silu(T1 @ Wn2 + bn2)
        launch_mma(NN, HD, HD, T1h, T1l, HD,
                   Wn2h + (size_t)l*HD*HD, Wn2l + (size_t)l*HD*HD, HD,
                   bh, HD, bn2 + l*HD, bh, nullptr, nullptr, FLAG_SILU);
    }

    // ---- epilogue ----
    ln_kernel<<<NN, 256>>>(bh, flng, flnb, bhF, cath, catl, 1024);
    posv_kernel<<<NN, 128>>>(Wc, out);
    cell_kernel<<<NB, HD>>>(numat, WL, bL, out + NN*3);
}

// round 11
// speedup vs baseline: 1.1648x; 1.0320x over previous
#include <cuda_runtime.h>
#include <cuda_bf16.h>
#include <math.h>
#include <stdint.h>

// ---------------- problem constants ----------------
#define NB    64
#define NPG   20
#define NN    (NB*NPG)          // 1280
#define NE    (NB*NPG*(NPG-1))  // 24320
#define NPAIR_G (NPG*(NPG-1)/2) // 190
#define NP    (NB*NPAIR_G)      // 12160
#define HD    512
#define TDm   256
#define NLAY  6
#define EINW  2313
#define DEG   (NPG-1)           // 19

#define TWO_PI_F 6.2831853071795864f

#define OFF_UD   0
#define OFF_SRC  3
#define OFF_DST  515
#define OFF_LAT  1027
#define OFF_FEMB 1033
#define OFF_NA   1801

#define FLAG_ACC   1
#define FLAG_SILU  2
#define FLAG_SPLIT 4

typedef unsigned long long u64;
typedef __nv_bfloat16 bf16;

// ---------------- scratch (device globals) ----------------
__device__ __align__(16) float g_h   [NN*HD];
__device__ __align__(16) float g_Xsd [NN*1024];   // [Xs | Xd]
__device__ __align__(16) float g_T1  [NN*HD];
__device__ __align__(16) float g_hF  [NN*HD];
__device__ __align__(16) float g_S   [(size_t)NLAY*NP*HD];   // per-layer
__device__ __align__(16) float g_C   [(size_t)NLAY*NP*HD];   // per-layer
__device__ __align__(16) float g_E2  [(size_t)NE*HD];
__device__ __align__(16) float g_ud  [NP*3];
__device__ __align__(16) float g_ltl [NB*9];
__device__ __align__(16) float g_econst[NLAY*NB*HD];
__device__ __align__(16) float g_v   [HD];
__device__ int g_arow[NN];

// bf16 activation planes
__device__ __align__(16) bf16 g_sch [(size_t)NP*768];
__device__ __align__(16) bf16 g_scl [(size_t)NP*768];
__device__ __align__(16) bf16 g_E1h [(size_t)NE*HD];
__device__ __align__(16) bf16 g_E1l [(size_t)NE*HD];
__device__ __align__(16) bf16 g_cath[NN*1024];    // [hn | agg]
__device__ __align__(16) bf16 g_catl[NN*1024];
__device__ __align__(16) bf16 g_T1h [NN*HD];
__device__ __align__(16) bf16 g_T1l [NN*HD];

// bf16 weight planes (K-major as in source)
__device__ __align__(16) bf16 g_Wsdh[(size_t)NLAY*HD*1024];  // [Wsrc|Wdst] packed
__device__ __align__(16) bf16 g_Wsdl[(size_t)NLAY*HD*1024];
__device__ __align__(16) bf16 g_Wfh [(size_t)NLAY*768*HD];
__device__ __align__(16) bf16 g_Wfl [(size_t)NLAY*768*HD];
__device__ __align__(16) bf16 g_We2h[(size_t)NLAY*HD*HD];
__device__ __align__(16) bf16 g_We2l[(size_t)NLAY*HD*HD];
__device__ __align__(16) bf16 g_Wn1h[(size_t)NLAY*2*HD*HD];
__device__ __align__(16) bf16 g_Wn1l[(size_t)NLAY*2*HD*HD];
__device__ __align__(16) bf16 g_Wn2h[(size_t)NLAY*HD*HD];
__device__ __align__(16) bf16 g_Wn2l[(size_t)NLAY*HD*HD];

// ---------------- helpers ----------------
__device__ __forceinline__ float warp_sum(float v){
    #pragma unroll
    for (int o = 16; o > 0; o >>= 1) v += __shfl_down_sync(0xffffffffu, v, o);
    return v;
}
__device__ __forceinline__ float silu_f(float v){ return v / (1.f + expf(-v)); }
__device__ __forceinline__ void splitf(float v, bf16 &h, bf16 &l){
    h = __float2bfloat16(v);
    l = __float2bfloat16(v - __bfloat162float(h));
}
__device__ __forceinline__ uint32_t sm_u32(const void* p){
    return (uint32_t)__cvta_generic_to_shared(p);
}
__device__ __forceinline__ void ldsm_x4(uint32_t &r0, uint32_t &r1, uint32_t &r2, uint32_t &r3, uint32_t a){
    asm volatile("ldmatrix.sync.aligned.m8n8.x4.shared.b16 {%0,%1,%2,%3}, [%4];"
        : "=r"(r0),"=r"(r1),"=r"(r2),"=r"(r3) : "r"(a));
}
__device__ __forceinline__ void ldsm_x4t(uint32_t &r0, uint32_t &r1, uint32_t &r2, uint32_t &r3, uint32_t a){
    asm volatile("ldmatrix.sync.aligned.m8n8.x4.trans.shared.b16 {%0,%1,%2,%3}, [%4];"
        : "=r"(r0),"=r"(r1),"=r"(r2),"=r"(r3) : "r"(a));
}
__device__ __forceinline__ void mma_bf16(float* c, const uint32_t* a, const uint32_t* b){
    asm volatile(
      "mma.sync.aligned.m16n8k16.row.col.f32.bf16.bf16.f32 "
      "{%0,%1,%2,%3}, {%4,%5,%6,%7}, {%8,%9}, {%0,%1,%2,%3};"
      : "+f"(c[0]),"+f"(c[1]),"+f"(c[2]),"+f"(c[3])
      : "r"(a[0]),"r"(a[1]),"r"(a[2]),"r"(a[3]), "r"(b[0]),"r"(b[1]));
}
__device__ __forceinline__ void cp16(uint32_t s, const void* g){
    asm volatile("cp.async.cg.shared.global [%0], [%1], 16;" :: "r"(s), "l"(g));
}
#define CP_COMMIT() asm volatile("cp.async.commit_group;" ::: "memory")
template<int N> __device__ __forceinline__ void cp_wait(){
    asm volatile("cp.async.wait_group %0;" :: "n"(N) : "memory");
}

// ---------------- split-bf16 tensor-core GEMM (proven 2-stage body) --------------
#define STG_ELEMS 18944
#define SMEM_MMA_BYTES (2*STG_ELEMS*2)

__device__ __forceinline__ void mm_load_stage(bf16* st, int tid,
    const bf16* __restrict__ Ah, const bf16* __restrict__ Al,
    const bf16* __restrict__ Bh, const bf16* __restrict__ Bl,
    int row0, int col0, int lda, int ldb, int k0)
{
    #pragma unroll
    for (int t = 0; t < 2; t++) {
        int lin = tid + t*256;
        int r = lin >> 2, c8 = (lin & 3) * 8;
        cp16(sm_u32(st +          r*40 + c8), Ah + (size_t)(row0+r)*lda + k0 + c8);
        cp16(sm_u32(st +  5120 +  r*40 + c8), Al + (size_t)(row0+r)*lda + k0 + c8);
        int rb = lin >> 4, cb = (lin & 15) * 8;
        cp16(sm_u32(st + 10240 + rb*136 + cb), Bh + (size_t)(k0+rb)*ldb + col0 + cb);
        cp16(sm_u32(st + 14592 + rb*136 + cb), Bl + (size_t)(k0+rb)*ldb + col0 + cb);
    }
    CP_COMMIT();
}

__device__ __forceinline__ void mm_compute_stage(const bf16* st, float acc[4][4][4],
                                                 int wm, int wn, int lane)
{
    const bf16* ah_ = st;
    const bf16* al_ = st + 5120;
    const bf16* bh_ = st + 10240;
    const bf16* bl_ = st + 14592;
    #pragma unroll
    for (int ks = 0; ks < 32; ks += 16) {
        uint32_t ah[4][4], al[4][4], bh[4][2], bl[4][2];
        #pragma unroll
        for (int mt = 0; mt < 4; mt++) {
            int rr = wm + mt*16 + (lane & 15);
            int cc = ks + (lane >> 4)*8;
            ldsm_x4(ah[mt][0],ah[mt][1],ah[mt][2],ah[mt][3], sm_u32(ah_ + rr*40 + cc));
            ldsm_x4(al[mt][0],al[mt][1],al[mt][2],al[mt][3], sm_u32(al_ + rr*40 + cc));
        }
        #pragma unroll
        for (int nt2 = 0; nt2 < 2; nt2++) {
            int rr = ks + (lane & 15);
            int cc = wn + nt2*16 + (lane >> 4)*8;
            uint32_t r0,r1,r2,r3;
            ldsm_x4t(r0,r1,r2,r3, sm_u32(bh_ + rr*136 + cc));
            bh[nt2*2][0]=r0; bh[nt2*2][1]=r1; bh[nt2*2+1][0]=r2; bh[nt2*2+1][1]=r3;
            ldsm_x4t(r0,r1,r2,r3, sm_u32(bl_ + rr*136 + cc));
            bl[nt2*2][0]=r0; bl[nt2*2][1]=r1; bl[nt2*2+1][0]=r2; bl[nt2*2+1][1]=r3;
        }
        #pragma unroll
        for (int mt = 0; mt < 4; mt++)
            #pragma unroll
            for (int nt = 0; nt < 4; nt++) {
                mma_bf16(acc[mt][nt], ah[mt], bh[nt]);
                mma_bf16(acc[mt][nt], ah[mt], bl[nt]);
                mma_bf16(acc[mt][nt], al[mt], bh[nt]);
            }
    }
}

__device__ __forceinline__ void gemm_body(int K,
    const bf16* __restrict__ Ah, const bf16* __restrict__ Al, int lda,
    const bf16* __restrict__ Bh, const bf16* __restrict__ Bl, int ldb,
    float* __restrict__ C, int ldc,
    const float* __restrict__ bias, const float* __restrict__ residual,
    bf16* __restrict__ Oh, bf16* __restrict__ Ol,
    int flags, int row0, int col0, char* dsmem)
{
    bf16* st0 = (bf16*)dsmem;
    bf16* st1 = st0 + STG_ELEMS;

    const int tid  = threadIdx.x;
    const int warp = tid >> 5, lane = tid & 31;
    const int wm = (warp >> 2) * 64;
    const int wn = (warp & 3) * 32;

    float acc[4][4][4];
    #pragma unroll
    for (int i = 0; i < 4; i++)
        #pragma unroll
        for (int j = 0; j < 4; j++)
            #pragma unroll
            for (int k = 0; k < 4; k++) acc[i][j][k] = 0.f;

    const int nch = K >> 5;
    mm_load_stage(st0, tid, Ah, Al, Bh, Bl, row0, col0, lda, ldb, 0);
    for (int kc = 0; kc < nch; kc++) {
        bf16* cur = (kc & 1) ? st1 : st0;
        bf16* nxt = (kc & 1) ? st0 : st1;
        if (kc + 1 < nch) {
            mm_load_stage(nxt, tid, Ah, Al, Bh, Bl, row0, col0, lda, ldb, (kc+1)*32);
            cp_wait<1>();
        } else {
            cp_wait<0>();
        }
        __syncthreads();
        mm_compute_stage(cur, acc, wm, wn, lane);
        __syncthreads();
    }

    #pragma unroll
    for (int mt = 0; mt < 4; mt++) {
        #pragma unroll
        for (int nt = 0; nt < 4; nt++) {
            #pragma unroll
            for (int half = 0; half < 2; half++) {
                int rr = row0 + wm + mt*16 + (lane >> 2) + half*8;
                int cc = col0 + wn + nt*8 + (lane & 3)*2;
                float v0 = acc[mt][nt][half*2 + 0];
                float v1 = acc[mt][nt][half*2 + 1];
                size_t o = (size_t)rr*ldc + cc;
                if (flags & FLAG_ACC)  { v0 += C[o]; v1 += C[o+1]; }
                if (bias)              { v0 += bias[cc]; v1 += bias[cc+1]; }
                if (flags & FLAG_SILU) { v0 = silu_f(v0); v1 = silu_f(v1); }
                if (residual)          { v0 += residual[o]; v1 += residual[o+1]; }
                *(float2*)(C + o) = make_float2(v0, v1);
                if (flags & FLAG_SPLIT) {
                    bf16 h0,l0,h1,l1;
                    splitf(v0,h0,l0); splitf(v1,h1,l1);
                    *(__nv_bfloat162*)(Oh + o) = __nv_bfloat162(h0, h1);
                    *(__nv_bfloat162*)(Ol + o) = __nv_bfloat162(l0, l1);
                }
            }
        }
    }
}

// general GEMM: grid (N/128, M/128)
__global__ __launch_bounds__(256)
void mma_gemm(int K,
    const bf16* __restrict__ Ah, const bf16* __restrict__ Al, int lda,
    const bf16* __restrict__ Bh, const bf16* __restrict__ Bl, int ldb,
    float* __restrict__ C, int ldc,
    const float* __restrict__ bias, const float* __restrict__ residual,
    bf16* __restrict__ Oh, bf16* __restrict__ Ol,
    int flags)
{
    extern __shared__ __align__(16) char dsmem[];
    gemm_body(K, Ah, Al, lda, Bh, Bl, ldb, C, ldc, bias, residual, Oh, Ol, flags,
              blockIdx.y*128, blockIdx.x*128, dsmem);
}

// all-layer femb GEMM: 4560 blocks = NLAY(6) * half(2:S,C) * (NP/128=95) * (HD/128=4)
__global__ __launch_bounds__(256)
void mma_gemm_femb(const bf16* __restrict__ sch, const bf16* __restrict__ scl,
                   const bf16* __restrict__ Wfh, const bf16* __restrict__ Wfl,
                   float* __restrict__ S, float* __restrict__ Cc)
{
    extern __shared__ __align__(16) char dsmem[];
    int bi = blockIdx.x;
    const int PER_L = 2*(NP/128)*(HD/128);      // 760
    int l = bi / PER_L, r = bi % PER_L;
    int half = r / ((NP/128)*(HD/128));
    int t = r % ((NP/128)*(HD/128));
    int row0 = (t / (HD/128)) * 128;
    int col0 = (t % (HD/128)) * 128;
    const bf16* Ah = sch + half*384;
    const bf16* Al = scl + half*384;
    const bf16* Bh = Wfh + (size_t)l*768*HD + (size_t)half*384*HD;
    const bf16* Bl = Wfl + (size_t)l*768*HD + (size_t)half*384*HD;
    float* C = (half ? Cc : S) + (size_t)l*NP*HD;
    gemm_body(384, Ah, Al, 768, Bh, Bl, HD, C, HD,
              nullptr, nullptr, nullptr, nullptr, 0, row0, col0, dsmem);
}

// ---------------- FFMA2 SGEMM (prologue h0 only) ----
__device__ __forceinline__ u64 pack2(float x, float y){
    u64 r; asm("mov.b64 %0, {%1, %2};" : "=l"(r) : "f"(x), "f"(y)); return r;
}
__device__ __forceinline__ void unpack2(u64 v, float &x, float &y){
    asm("mov.b64 {%0, %1}, %2;" : "=f"(x), "=f"(y) : "l"(v));
}
__device__ __forceinline__ void ffma2(u64 &acc, u64 a, u64 b){
    asm("fma.rn.f32x2 %0, %1, %2, %0;" : "+l"(acc) : "l"(a), "l"(b));
}
template<int BM,int BN,int BK,int TM,int TN>
__global__ __launch_bounds__((BM/TM)*(BN/TN))
void sgemm2_kernel(int M, int N, int K,
                   const float* __restrict__ A, int lda,
                   const float* __restrict__ B, int ldb,
                   float* __restrict__ C, int ldc,
                   const int* __restrict__ arow)
{
    __shared__ __align__(16) float As[BK][BM];
    __shared__ __align__(16) float Bs[BK][BN];
    const int tid = threadIdx.x;
    const int tx  = tid % (BN/TN);
    const int ty  = tid / (BN/TN);
    const int row0 = blockIdx.y * BM;
    const int col0 = blockIdx.x * BN;
    constexpr int AVPR = BK/4;
    const int a_r = tid / AVPR;
    const int a_c = (tid % AVPR) * 4;
    constexpr int BVPR = BN/4;
    const int b_r = tid / BVPR;
    const int b_c = (tid % BVPR) * 4;
    const float* Arow = A + (size_t)(arow ? arow[row0 + a_r] : (row0 + a_r)) * lda;

    u64 acc[TM][TN/2];
    #pragma unroll
    for (int i = 0; i < TM; i++)
        #pragma unroll
        for (int j = 0; j < TN/2; j++) acc[i][j] = 0ull;

    for (int k0 = 0; k0 < K; k0 += BK) {
        float4 av = *(const float4*)(Arow + k0 + a_c);
        As[a_c+0][a_r] = av.x; As[a_c+1][a_r] = av.y;
        As[a_c+2][a_r] = av.z; As[a_c+3][a_r] = av.w;
        *(float4*)&Bs[b_r][b_c] = *(const float4*)(B + (size_t)(k0 + b_r)*ldb + col0 + b_c);
        __syncthreads();
        #pragma unroll
        for (int kk = 0; kk < BK; kk++) {
            float a[TM];
            #pragma unroll
            for (int i = 0; i < TM; i += 4) {
                float4 t = *(const float4*)&As[kk][ty*TM + i];
                a[i]=t.x; a[i+1]=t.y; a[i+2]=t.z; a[i+3]=t.w;
            }
            u64 ap[TM];
            #pragma unroll
            for (int i = 0; i < TM; i++) ap[i] = pack2(a[i], a[i]);
            u64 bp[TN/2];
            #pragma unroll
            for (int j = 0; j < TN/2; j += 2) {
                ulonglong2 t = *(const ulonglong2*)&Bs[kk][tx*TN + 2*j];
                bp[j] = t.x; bp[j+1] = t.y;
            }
            #pragma unroll
            for (int i = 0; i < TM; i++)
                #pragma unroll
                for (int j = 0; j < TN/2; j++)
                    ffma2(acc[i][j], ap[i], bp[j]);
        }
        __syncthreads();
    }
    #pragma unroll
    for (int i = 0; i < TM; i++) {
        const int r = row0 + ty*TM + i;
        #pragma unroll
        for (int j = 0; j < TN/2; j++) {
            const int c = col0 + tx*TN + 2*j;
            float v0, v1; unpack2(acc[i][j], v0, v1);
            C[(size_t)r*ldc + c]   = v0;
            C[(size_t)r*ldc + c+1] = v1;
        }
    }
}

// ---------------- glue kernels ----------------
__global__ void split_kernel(const float* __restrict__ in, bf16* __restrict__ oh,
                             bf16* __restrict__ ol, int n){
    int i = blockIdx.x*256 + threadIdx.x;
    if (i < n) { bf16 h,l; splitf(in[i], h, l); oh[i]=h; ol[i]=l; }
}

// all-layer pack [Wsrc | Wdst] (NLAY x 512 x 1024) and split
__global__ void pack_sd_kernel(const float* __restrict__ We1,
                               bf16* __restrict__ oh, bf16* __restrict__ ol){
    int idx = blockIdx.x*256 + threadIdx.x;   // NLAY*512*1024 total
    int l = idx >> 19;                         // / (512*1024)
    int rem = idx & ((512*1024)-1);
    int k = rem >> 10, c = rem & 1023;
    const float* W = We1 + (size_t)l*EINW*HD;
    float v = (c < 512) ? W[(size_t)(OFF_SRC + k)*HD + c]
                        : W[(size_t)(OFF_DST + k)*HD + (c - 512)];
    bf16 h,l2; splitf(v,h,l2);
    oh[idx]=h; ol[idx]=l2;
}

// all-layer femb weight split (strided gather from We1 slabs)
__global__ void split_femb_kernel(const float* __restrict__ We1,
                                  bf16* __restrict__ oh, bf16* __restrict__ ol){
    int idx = blockIdx.x*256 + threadIdx.x;   // NLAY*768*HD total
    int l = idx / (768*HD);
    int rem = idx - l*(768*HD);
    float v = We1[(size_t)l*EINW*HD + (size_t)OFF_FEMB*HD + rem];
    bf16 h,l2; splitf(v,h,l2);
    oh[idx]=h; ol[idx]=l2;
}

__global__ void atomidx_kernel(const int* __restrict__ at){
    int n = blockIdx.x*256 + threadIdx.x;
    if (n < NN) g_arow[n] = max(at[n]-1, 0);
}

__global__ void vtime_kernel(const float* __restrict__ Wt, const float* __restrict__ Wl){
    int j = blockIdx.x*256 + threadIdx.x;
    if (j >= HD) return;
    float acc = 0.f;
    for (int k = 0; k < TDm; k++) acc += Wt[k] * Wl[(size_t)(HD + k)*HD + j];
    g_v[j] = acc;
}

__global__ void add_tv_kernel(const float* __restrict__ t, const int* __restrict__ n2g){
    int n = blockIdx.x; int j = threadIdx.x;
    g_h[(size_t)n*HD + j] += t[n2g[n]] * g_v[j];
}

__global__ void lattice_kernel(const float* __restrict__ lp){
    int b = blockIdx.x*64 + threadIdx.x;
    if (b >= NB) return;
    const float LM[3] = {1.575442910194397f, 1.7017393112182617f, 1.9781638383865356f};
    const float LS[3] = {0.24437622725963593f, 0.26526379585266113f, 0.3535512685775757f};
    float len[3], ang[3];
    #pragma unroll
    for (int i = 0; i < 3; i++) {
        len[i] = expf(lp[b*6+i]*LS[i] + LM[i]);
        float x = lp[b*6+3+i];
        float sg = 1.f/(1.f+expf(-x));
        ang[i] = (59.9f + 60.2f*sg) * (3.14159265358979323846f/180.f);
    }
    float c0=cosf(ang[0]), c1=cosf(ang[1]), c2=cosf(ang[2]);
    float s0=sinf(ang[0]), s1=sinf(ang[1]);
    float val = (c0*c1 - c2) / (s0*s1);
    val = fminf(1.f, fmaxf(-1.f, val));
    float gs = acosf(val);
    float L[3][3];
    L[0][0]=len[0]*s1;            L[0][1]=0.f;                 L[0][2]=len[0]*c1;
    L[1][0]=-len[1]*s0*cosf(gs);  L[1][1]=len[1]*s0*sinf(gs);  L[1][2]=len[1]*c0;
    L[2][0]=0.f;                  L[2][1]=0.f;                 L[2][2]=len[2];
    #pragma unroll
    for (int i = 0; i < 3; i++)
        #pragma unroll
        for (int k = 0; k < 3; k++)
            g_ltl[b*9 + i*3 + k] = L[i][0]*L[k][0] + L[i][1]*L[k][1] + L[i][2]*L[k][2];
}

__global__ void pair_geom_kernel(const float* __restrict__ fc)
{
    const int p = blockIdx.x;
    __shared__ float d[3];
    if (threadIdx.x == 0) {
        int g = p / NPAIR_G, q = p % NPAIR_G;
        int i = 0, base = 0;
        while (base + (DEG - i) <= q) { base += DEG - i; i++; }
        int j = i + 1 + (q - base);
        int ni = g*NPG + i, nj = g*NPG + j;
        float dd[3];
        #pragma unroll
        for (int k = 0; k < 3; k++) {
            float z = TWO_PI_F * (fc[nj*3+k] - fc[ni*3+k]);
            dd[k] = atan2f(sinf(z), cosf(z)) * (1.f/TWO_PI_F);
        }
        float dot[3];
        #pragma unroll
        for (int k = 0; k < 3; k++)
            dot[k] = g_ltl[g*9+k*3+0]*dd[0] + g_ltl[g*9+k*3+1]*dd[1] + g_ltl[g*9+k*3+2]*dd[2];
        float nrm = sqrtf(dot[0]*dot[0] + dot[1]*dot[1] + dot[2]*dot[2]) + 1e-12f;
        #pragma unroll
        for (int k = 0; k < 3; k++) {
            g_ud[p*3+k] = dot[k] / nrm;
            d[k] = dd[k];
        }
    }
    __syncthreads();
    int idx = threadIdx.x;          // 384 threads
    int dim = idx >> 7, k = idx & 127;
    float ang = d[dim] * (TWO_PI_F * (float)k);
    float s, c; sincosf(ang, &s, &c);
    bf16 h,l;
    splitf(s,h,l);
    g_sch[(size_t)p*768 + idx] = h; g_scl[(size_t)p*768 + idx] = l;
    splitf(c,h,l);
    g_sch[(size_t)p*768 + 384 + idx] = h; g_scl[(size_t)p*768 + 384 + idx] = l;
}

__global__ void econst_kernel(const float* __restrict__ We1, const float* __restrict__ be1,
                              const float* __restrict__ Wna, const float* __restrict__ lp,
                              const int* __restrict__ numat)
{
    const int l = blockIdx.x / NB, b = blockIdx.x % NB;
    const int j = threadIdx.x;
    const float* W = We1 + (size_t)l*EINW*HD;
    float acc = be1[l*HD + j];
    #pragma unroll
    for (int k = 0; k < 6; k++)
        acc += lp[b*6+k] * W[(size_t)(OFF_LAT+k)*HD + j];
    const float* na = Wna + (size_t)l*100*HD + (size_t)max(numat[b]-1,0)*HD;
    const float* Wna_base = W + (size_t)OFF_NA*HD + j;
    float a0 = 0.f, a1 = 0.f, a2 = 0.f, a3 = 0.f;
    for (int k = 0; k < HD; k += 4) {
        a0 += na[k+0] * Wna_base[(size_t)(k+0)*HD];
        a1 += na[k+1] * Wna_base[(size_t)(k+1)*HD];
        a2 += na[k+2] * Wna_base[(size_t)(k+2)*HD];
        a3 += na[k+3] * Wna_base[(size_t)(k+3)*HD];
    }
    acc += (a0 + a1) + (a2 + a3);
    g_econst[((size_t)l*NB + b)*HD + j] = acc;
}

// LayerNorm; optional fp32 out (stride HD) + bf16 planes (stride ldp)
__global__ void ln_kernel(const float* __restrict__ x, const float* __restrict__ g,
                          const float* __restrict__ b, float* __restrict__ y,
                          bf16* __restrict__ yh, bf16* __restrict__ yl, int ldp)
{
    const int n = blockIdx.x;
    const int j = threadIdx.x;
    const float* xr = x + (size_t)n*HD;
    float v0 = xr[j], v1 = xr[j+256];
    __shared__ float sh[8];
    int lane = j & 31, w = j >> 5;
    float s = warp_sum(v0 + v1);
    if (lane == 0) sh[w] = s;
    __syncthreads();
    if (w == 0) { float t = (lane < 8) ? sh[lane] : 0.f; t = warp_sum(t); if (lane==0) sh[0]=t; }
    __syncthreads();
    float mean = sh[0] * (1.f/HD);
    __syncthreads();
    float d0 = v0 - mean, d1 = v1 - mean;
    float q = warp_sum(d0*d0 + d1*d1);
    if (lane == 0) sh[w] = q;
    __syncthreads();
    if (w == 0) { float t = (lane < 8) ? sh[lane] : 0.f; t = warp_sum(t); if (lane==0) sh[0]=t; }
    __syncthreads();
    float inv = rsqrtf(sh[0]*(1.f/HD) + 1e-5f);
    float o0 = d0*inv*g[j]     + b[j];
    float o1 = d1*inv*g[j+256] + b[j+256];
    if (y) {
        y[(size_t)n*HD + j]     = o0;
        y[(size_t)n*HD + j+256] = o1;
    }
    bf16 hh,ll;
    splitf(o0,hh,ll); yh[(size_t)n*ldp+j]=hh;     yl[(size_t)n*ldp+j]=ll;
    splitf(o1,hh,ll); yh[(size_t)n*ldp+j+256]=hh; yl[(size_t)n*ldp+j+256]=ll;
}

// Pairwise combine: one block per unordered pair computes BOTH directed edges.
// v_fwd = C + S + Xs[a] + Xd[b] + ec + u.W ; v_bwd = C - S + Xs[b] + Xd[a] + ec - u.W
__global__ void combine_pair_kernel(const float* __restrict__ We1ud,
                                    const float* __restrict__ econst_l,
                                    const float* __restrict__ Sl,
                                    const float* __restrict__ Cl)
{
    const int p = blockIdx.x;              // 0..NP-1
    const int g = p / NPAIR_G;
    int q = p % NPAIR_G;
    int a = 0, base = 0;
    while (base + (DEG - a) <= q) { base += DEG - a; a++; }
    const int b = a + 1 + (q - base);      // a < b

    // directed edge indices
    const int e_fwd = g*(NPG*DEG) + a*DEG + (b - 1);   // a -> b (b > a)
    const int e_bwd = g*(NPG*DEG) + b*DEG + a;         // b -> a (a < b)
    const int na_ = g*NPG + a, nb_ = g*NPG + b;

    const float u0 = g_ud[p*3+0], u1 = g_ud[p*3+1], u2 = g_ud[p*3+2];
    const float* Sv = Sl + (size_t)p*HD;
    const float* Cv = Cl + (size_t)p*HD;
    const float* xsa = g_Xsd + (size_t)na_*1024;        // Xs[a]
    const float* xda = g_Xsd + (size_t)na_*1024 + 512;  // Xd[a]
    const float* xsb = g_Xsd + (size_t)nb_*1024;        // Xs[b]
    const float* xdb = g_Xsd + (size_t)nb_*1024 + 512;  // Xd[b]
    const float* ec = econst_l + (size_t)g*HD;
    bf16* ofh = g_E1h + (size_t)e_fwd*HD;
    bf16* ofl = g_E1l + (size_t)e_fwd*HD;
    bf16* obh = g_E1h + (size_t)e_bwd*HD;
    bf16* obl = g_E1l + (size_t)e_bwd*HD;

    for (int c = threadIdx.x; c < HD; c += 256) {
        float sv = Sv[c], cv = Cv[c], e = ec[c];
        float w = u0*We1ud[c] + u1*We1ud[HD+c] + u2*We1ud[2*HD+c];
        float vf = cv + sv + xsa[c] + xdb[c] + e + w;
        float vb = cv - sv + xsb[c] + xda[c] + e - w;
        vf = silu_f(vf);
        vb = silu_f(vb);
        bf16 h,l;
        splitf(vf,h,l); ofh[c]=h; ofl[c]=l;
        splitf(vb,h,l); obh[c]=h; obl[c]=l;
    }
}

// agg[n] = mean over 19 contiguous edges -> cat planes (offset 512, stride 1024)
__global__ void agg_kernel(){
    const int n = blockIdx.x;
    const float* p = g_E2 + (size_t)n*DEG*HD;
    for (int j = threadIdx.x; j < HD; j += 256) {
        float s = 0.f;
        #pragma unroll
        for (int i = 0; i < DEG; i++) s += p[(size_t)i*HD + j];
        s *= (1.f/(float)DEG);
        bf16 h,l; splitf(s,h,l);
        g_cath[(size_t)n*1024 + 512 + j] = h;
        g_catl[(size_t)n*1024 + 512 + j] = l;
    }
}

__global__ void posv_kernel(const float* __restrict__ Wc, float* __restrict__ out){
    const int n = blockIdx.x;
    float a0=0.f, a1=0.f, a2=0.f;
    for (int k = threadIdx.x; k < HD; k += 128) {
        float hv = g_hF[(size_t)n*HD + k];
        a0 += hv*Wc[k*3+0]; a1 += hv*Wc[k*3+1]; a2 += hv*Wc[k*3+2];
    }
    a0 = warp_sum(a0); a1 = warp_sum(a1); a2 = warp_sum(a2);
    __shared__ float sh[4][3];
    int lane = threadIdx.x & 31, w = threadIdx.x >> 5;
    if (lane == 0) { sh[w][0]=a0; sh[w][1]=a1; sh[w][2]=a2; }
    __syncthreads();
    if (threadIdx.x < 3) {
        float s = sh[0][threadIdx.x] + sh[1][threadIdx.x] + sh[2][threadIdx.x] + sh[3][threadIdx.x];
        out[n*3 + threadIdx.x] = s;
    }
}

__global__ void cell_kernel(const int* __restrict__ numat, const float* __restrict__ WL,
                            const float* __restrict__ bL, float* __restrict__ out)
{
    const int b = blockIdx.x;
    const int j = threadIdx.x;
    float cs = 0.f;
    #pragma unroll
    for (int i = 0; i < NPG; i++) cs += g_hF[(size_t)(b*NPG+i)*HD + j];
    float inv_na = 1.f / (float)numat[b];
    float contrib[6];
    #pragma unroll
    for (int c = 0; c < 6; c++)
        contrib[c] = cs * (WL[j*6+c]*inv_na + WL[(HD+j)*6+c]);
    __shared__ float sh[16][6];
    int lane = j & 31, w = j >> 5;
    #pragma unroll
    for (int c = 0; c < 6; c++) {
        float v = warp_sum(contrib[c]);
        if (lane == 0) sh[w][c] = v;
    }
    __syncthreads();
    if (w == 0) {
        #pragma unroll
        for (int c = 0; c < 6; c++) {
            float v = (lane < 16) ? sh[lane][c] : 0.f;
            v = warp_sum(v);
            if (lane == 0) out[b*6 + c] = bL[c] + v;
        }
    }
}

// ---------------- host ----------------
static inline void launch_mma(int M, int N, int K,
                              const bf16* Ah, const bf16* Al, int lda,
                              const bf16* Bh, const bf16* Bl, int ldb,
                              float* C, int ldc,
                              const float* bias, const float* res,
                              bf16* Oh, bf16* Ol, int flags){
    dim3 g(N/128, M/128);
    mma_gemm<<<g, 256, SMEM_MMA_BYTES>>>(K, Ah, Al, lda, Bh, Bl, ldb, C, ldc, bias, res, Oh, Ol, flags);
}

extern "C" void kernel_launch(void* const* d_in, const int* in_sizes, int n_in,
                              void* d_out, int out_size)
{
    const float* t_in   = (const float*)d_in[0];
    const float* fc     = (const float*)d_in[1];
    const float* lp     = (const float*)d_in[2];
    const int*   at     = (const int*)  d_in[3];
    const int*   numat  = (const int*)  d_in[4];
    const int*   n2g    = (const int*)  d_in[5];
    const float* W_node = (const float*)d_in[8];
    const float* W_time = (const float*)d_in[9];
    const float* W_lat  = (const float*)d_in[10];
    const float* ln_g   = (const float*)d_in[11];
    const float* ln_b   = (const float*)d_in[12];
    const float* We1    = (const float*)d_in[13];
    const float* be1    = (const float*)d_in[14];
    const float* We2    = (const float*)d_in[15];
    const float* be2    = (const float*)d_in[16];
    const float* Wn1    = (const float*)d_in[17];
    const float* bn1    = (const float*)d_in[18];
    const float* Wn2    = (const float*)d_in[19];
    const float* bn2    = (const float*)d_in[20];
    const float* Wna    = (const float*)d_in[21];
    const float* flng   = (const float*)d_in[22];
    const float* flnb   = (const float*)d_in[23];
    const float* Wc     = (const float*)d_in[24];
    const float* WL     = (const float*)d_in[25];
    const float* bL     = (const float*)d_in[26];
    float* out = (float*)d_out;
    (void)in_sizes; (void)n_in; (void)out_size;

    cudaFuncSetAttribute(mma_gemm, cudaFuncAttributeMaxDynamicSharedMemorySize, SMEM_MMA_BYTES);
    cudaFuncSetAttribute(mma_gemm_femb, cudaFuncAttributeMaxDynamicSharedMemorySize, SMEM_MMA_BYTES);

    #define SYMA(T, var, sym) T* var; { void* p_; cudaGetSymbolAddress(&p_, sym); var = (T*)p_; }
    SYMA(float, bh,   g_h)    SYMA(float, bXsd, g_Xsd)
    SYMA(float, bT1,  g_T1)   SYMA(float, bhF, g_hF)
    SYMA(float, bS,   g_S)    SYMA(float, bC,   g_C)    SYMA(float, bE2, g_E2)
    SYMA(float, bec,  g_econst)
    SYMA(int,   barow,g_arow)
    SYMA(bf16,  sch,  g_sch)  SYMA(bf16, scl,  g_scl)
    SYMA(bf16,  E1h,  g_E1h)  SYMA(bf16, E1l,  g_E1l)
    SYMA(bf16,  cath, g_cath) SYMA(bf16, catl, g_catl)
    SYMA(bf16,  T1h,  g_T1h)  SYMA(bf16, T1l,  g_T1l)
    SYMA(bf16,  Wsdh, g_Wsdh) SYMA(bf16, Wsdl, g_Wsdl)
    SYMA(bf16,  Wfh,  g_Wfh)  SYMA(bf16, Wfl,  g_Wfl)
    SYMA(bf16,  We2h, g_We2h) SYMA(bf16, We2l, g_We2l)
    SYMA(bf16,  Wn1h, g_Wn1h) SYMA(bf16, Wn1l, g_Wn1l)
    SYMA(bf16,  Wn2h, g_Wn2h) SYMA(bf16, Wn2l, g_Wn2l)
    #undef SYMA

    // ---- prologue ----
    atomidx_kernel<<<(NN+255)/256, 256>>>(at);
    lattice_kernel<<<1, 64>>>(lp);
    vtime_kernel<<<(HD+255)/256, 256>>>(W_time, W_lat);
    pair_geom_kernel<<<NP, 384>>>(fc);
    econst_kernel<<<NLAY*NB, HD>>>(We1, be1, Wna, lp, numat);

    // weight packing/splitting (all layers, consolidated launches)
    pack_sd_kernel<<<(NLAY*HD*1024)/256, 256>>>(We1, Wsdh, Wsdl);
    split_femb_kernel<<<(NLAY*768*HD)/256, 256>>>(We1, Wfh, Wfl);
    { int n = NLAY*HD*HD;   split_kernel<<<(n+255)/256,256>>>(We2, We2h, We2l, n); }
    { int n = NLAY*2*HD*HD; split_kernel<<<(n+255)/256,256>>>(Wn1, Wn1h, Wn1l, n); }
    { int n = NLAY*HD*HD;   split_kernel<<<(n+255)/256,256>>>(Wn2, Wn2h, Wn2l, n); }

    // all-layer femb GEMMs: S[l], C[l] for l = 0..5 in one launch (4560 blocks)
    mma_gemm_femb<<<NLAY*2*(NP/128)*(HD/128), 256, SMEM_MMA_BYTES>>>(sch, scl, Wfh, Wfl, bS, bC);

    // h0 = W_node[at-1] @ W_latent[0:512] (+ t*v)
    {
        dim3 g(HD/64, NN/64);
        sgemm2_kernel<64,64,16,4,4><<<g, 256>>>(NN, HD, HD, W_node, HD, W_lat, HD, bh, HD, barow);
    }
    add_tv_kernel<<<NN, HD>>>(t_in, n2g);

    // ---- layers ----
    for (int l = 0; l < NLAY; l++) {
        const float* We1_l = We1 + (size_t)l*EINW*HD;

        ln_kernel<<<NN, 256>>>(bh, ln_g + l*HD, ln_b + l*HD, nullptr, cath, catl, 1024);

        // [Xs|Xd] = hn @ [Wsrc|Wdst]
        launch_mma(NN, 1024, HD, cath, catl, 1024,
                   Wsdh + (size_t)l*HD*1024, Wsdl + (size_t)l*HD*1024, 1024,
                   bXsd, 1024, nullptr, nullptr, nullptr, nullptr, 0);

        combine_pair_kernel<<<NP, 256>>>(We1_l + (size_t)OFF_UD*HD, bec + (size_t)l*NB*HD,
                                         bS + (size_t)l*NP*HD, bC + (size_t)l*NP*HD);

        // E2 = silu(E1 @ We2 + be2)
        launch_mma(NE, HD, HD, E1h, E1l, HD,
                   We2h + (size_t)l*HD*HD, We2l + (size_t)l*HD*HD, HD,
                   bE2, HD, be2 + l*HD, nullptr, nullptr, nullptr, FLAG_SILU);

        agg_kernel<<<NN, 256>>>();

        // T1 = silu([hn|agg] @ Wn1 + bn1)  (K=1024)
        launch_mma(NN, HD, 1024, cath, catl, 1024,
                   Wn1h + (size_t)l*2*HD*HD, Wn1l + (size_t)l*2*HD*HD, HD,
                   bT1, HD, bn1 + l*HD, nullptr, T1h, T1l, FLAG_SILU|FLAG_SPLIT);
        // h = h + silu(T1 @ Wn2 + bn2)
        launch_mma(NN, HD, HD, T1h, T1l, HD,
                   Wn2h + (size_t)l*HD*HD, Wn2l + (size_t)l*HD*HD, HD,
                   bh, HD, bn2 + l*HD, bh, nullptr, nullptr, FLAG_SILU);
    }

    // ---- epilogue ----
    ln_kernel<<<NN, 256>>>(bh, flng, flnb, bhF, cath, catl, 1024);
    posv_kernel<<<NN, 128>>>(Wc, out);
    cell_kernel<<<NB, HD>>>(numat, WL, bL, out + NN*3);
}